// round 3
// baseline (speedup 1.0000x reference)
#include <cuda_runtime.h>
#include <math.h>
#include <stdint.h>

#define B_  4
#define T_  2048
#define E_  1024
#define H_  16
#define D_  64
#define F_  32
#define M_  (B_*T_)     // 8192
#define N3_ (3*E_)      // 3072

typedef unsigned long long ull;

// Scratch (device globals; no allocation allowed)
__device__ float g_q[B_*H_*T_*D_];
__device__ float g_k[B_*H_*T_*D_];
__device__ float g_v[B_*H_*T_*D_];
__device__ float g_attn[M_*E_];

// ---------------------------------------------------------------------------
// packed f32x2 helpers (base sm_100 feature, NOT 'a'-gated)
// ---------------------------------------------------------------------------
__device__ __forceinline__ ull fma2(ull a, ull b, ull c) {
    ull d;
    asm("fma.rn.f32x2 %0, %1, %2, %3;" : "=l"(d) : "l"(a), "l"(b), "l"(c));
    return d;
}
__device__ __forceinline__ ull pack2(float x, float y) {
    ull r;
    asm("mov.b64 %0, {%1, %2};" : "=l"(r) : "f"(x), "f"(y));
    return r;
}
__device__ __forceinline__ ull dup2(float x) {
    ull r;
    asm("mov.b64 %0, {%1, %1};" : "=l"(r) : "f"(x));
    return r;
}
__device__ __forceinline__ float2 unpack2(ull v) {
    float2 o;
    asm("mov.b64 {%0, %1}, %2;" : "=f"(o.x), "=f"(o.y) : "l"(v));
    return o;
}

// ---------------------------------------------------------------------------
// GEMM-NT: C[m,n] = sum_k A[m,k] * W[n,k] + bias[n]   (f32x2 inner product)
//   mode 1: A = A_in (query), scatter C into g_q/g_k/g_v head-major layout
//   mode 2: A = g_attn, C = plain row-major output
// Tiles: BM=BN=128, BK=8, 256 threads, 8x8 per-thread micro-tile.
// ---------------------------------------------------------------------------
__global__ __launch_bounds__(256)
void gemm_kernel(const float* __restrict__ A_in,
                 const float* __restrict__ W,
                 const float* __restrict__ bias,
                 float* __restrict__ C,
                 int N, int K, int mode)
{
    const float* A = (mode == 2) ? g_attn : A_in;

    __shared__ float As[8][132];
    __shared__ float Bs[8][132];

    const int tid  = threadIdx.x;
    const int row0 = blockIdx.y * 128;
    const int col0 = blockIdx.x * 128;

    const int tr = (tid >> 4) << 3;   // 0..120 step 8 (output rows)
    const int tc = (tid & 15) << 3;   // 0..120 step 8 (output cols)

    const int lr = tid >> 1;          // 0..127 (load row)
    const int lc = (tid & 1) << 2;    // 0 or 4 (load col within k-tile)

    ull acc2[8][4];                   // 8 rows x 4 col-pairs
#pragma unroll
    for (int i = 0; i < 8; i++)
#pragma unroll
        for (int j = 0; j < 4; j++) acc2[i][j] = 0ull;

    const float* Aptr = A + (size_t)(row0 + lr) * K + lc;
    const float* Wptr = W + (size_t)(col0 + lr) * K + lc;

    for (int kt = 0; kt < K; kt += 8) {
        float4 av = *(const float4*)(Aptr + kt);
        float4 bv = *(const float4*)(Wptr + kt);
        As[lc + 0][lr] = av.x; As[lc + 1][lr] = av.y;
        As[lc + 2][lr] = av.z; As[lc + 3][lr] = av.w;
        Bs[lc + 0][lr] = bv.x; Bs[lc + 1][lr] = bv.y;
        Bs[lc + 2][lr] = bv.z; Bs[lc + 3][lr] = bv.w;
        __syncthreads();

#pragma unroll
        for (int kk = 0; kk < 8; kk++) {
            float ra[8];
#pragma unroll
            for (int i = 0; i < 8; i++) ra[i] = As[kk][tr + i];
            const float4 b0 = *(const float4*)&Bs[kk][tc];
            const float4 b1 = *(const float4*)&Bs[kk][tc + 4];
            ull rb2[4];
            rb2[0] = pack2(b0.x, b0.y); rb2[1] = pack2(b0.z, b0.w);
            rb2[2] = pack2(b1.x, b1.y); rb2[3] = pack2(b1.z, b1.w);
#pragma unroll
            for (int i = 0; i < 8; i++) {
                const ull a2 = dup2(ra[i]);
#pragma unroll
                for (int j = 0; j < 4; j++)
                    acc2[i][j] = fma2(a2, rb2[j], acc2[i][j]);
            }
        }
        __syncthreads();
    }

    // Epilogue
    if (mode == 1) {
        const int sec = col0 >> 10;    // 0=q,1=k,2=v (tile fully inside one section)
        float* dst_base = (sec == 0) ? g_q : (sec == 1) ? g_k : g_v;
#pragma unroll
        for (int i = 0; i < 8; i++) {
            const int m = row0 + tr + i;
            const int b = m >> 11;
            const int t = m & 2047;
#pragma unroll
            for (int j = 0; j < 4; j++) {
                const float2 v = unpack2(acc2[i][j]);
                const int n0 = col0 + tc + 2 * j;
                const int nn0 = n0 & 1023;
                const int h   = nn0 >> 6;
                const int d   = nn0 & 63;
                float* dst = dst_base + ((size_t)(b * H_ + h) * T_ + t) * D_ + d;
                dst[0] = v.x + bias[n0];
                dst[1] = v.y + bias[n0 + 1];
            }
        }
    } else {
#pragma unroll
        for (int i = 0; i < 8; i++) {
            const int m = row0 + tr + i;
            float* dst = C + (size_t)m * N + col0 + tc;
#pragma unroll
            for (int j = 0; j < 4; j++) {
                const float2 v = unpack2(acc2[i][j]);
                const int n0 = col0 + tc + 2 * j;
                dst[2 * j]     = v.x + bias[n0];
                dst[2 * j + 1] = v.y + bias[n0 + 1];
            }
        }
    }
}

// ---------------------------------------------------------------------------
// Rotary: one thread per (b,h,t,f). cos/sin shared between Q and K.
// ---------------------------------------------------------------------------
__global__ __launch_bounds__(256)
void rotary_kernel(const float* __restrict__ pos, const float* __restrict__ freqs)
{
    const int idx = blockIdx.x * blockDim.x + threadIdx.x;
    const int f = idx & 31;
    const int t = (idx >> 5) & 2047;
    const int h = (idx >> 16) & 15;
    const int b = idx >> 20;

    const float* p  = pos   + ((size_t)b * T_ + t) * 3;
    const float* fr = freqs + ((size_t)h * F_ + f) * 3;
    const float ang = p[0] * fr[0] + p[1] * fr[1] + p[2] * fr[2];
    float s, c;
    sincosf(ang, &s, &c);

    const size_t base = ((size_t)(b * H_ + h) * T_ + t) * D_ + 2 * f;
    const float q0 = g_q[base], q1 = g_q[base + 1];
    g_q[base]     = q0 * c - q1 * s;
    g_q[base + 1] = q0 * s + q1 * c;
    const float k0 = g_k[base], k1 = g_k[base + 1];
    g_k[base]     = k0 * c - k1 * s;
    g_k[base + 1] = k0 * s + k1 * c;
}

// ---------------------------------------------------------------------------
// Flash attention, fp32 with f32x2 inner products.
// Block = one (b,h) x 64-query tile; 256 threads. Smem stride 66 (8B aligned).
// ---------------------------------------------------------------------------
#define FA_STRIDE 66
#define FA_SMEM_FLOATS (4 * 64 * FA_STRIDE + 3 * 64)

__global__ __launch_bounds__(256)
void flash_kernel()
{
    extern __shared__ float sm[];
    float* Qs   = sm;                         // 64 x 66
    float* Ks   = sm + 64 * FA_STRIDE;
    float* Vs   = sm + 2 * 64 * FA_STRIDE;
    float* Ss   = sm + 3 * 64 * FA_STRIDE;
    float* rowm = sm + 4 * 64 * FA_STRIDE;    // 64
    float* rowl = rowm + 64;
    float* rowf = rowl + 64;

    const int tid = threadIdx.x;
    const int bh  = blockIdx.y;
    const int q0  = blockIdx.x * 64;

    const float2* Qg = (const float2*)(g_q + ((size_t)bh * T_ + q0) * D_);
    const float2* Kg = (const float2*)(g_k + (size_t)bh * T_ * D_);
    const float2* Vg = (const float2*)(g_v + (size_t)bh * T_ * D_);

    // Q tile (64x64 = 2048 float2)
    for (int i2 = tid; i2 < 2048; i2 += 256) {
        const int r = i2 >> 5, c2 = i2 & 31;
        *(float2*)&Qs[r * FA_STRIDE + 2 * c2] = Qg[i2];
    }
    if (tid < 64) { rowm[tid] = -INFINITY; rowl[tid] = 0.f; }

    const int sr = (tid >> 4) << 2;   // 4 output rows
    const int sc = (tid & 15) << 2;   // 4 output cols

    float o[4][4];
#pragma unroll
    for (int i = 0; i < 4; i++)
#pragma unroll
        for (int j = 0; j < 4; j++) o[i][j] = 0.f;

    for (int j0 = 0; j0 < T_; j0 += 64) {
        __syncthreads();  // protect Ks/Vs/Ss reuse; also fences Q load (iter 0)
        for (int i2 = tid; i2 < 2048; i2 += 256) {
            const int r = i2 >> 5, c2 = i2 & 31;
            *(float2*)&Ks[r * FA_STRIDE + 2 * c2] = Kg[(size_t)j0 * 32 + i2];
            *(float2*)&Vs[r * FA_STRIDE + 2 * c2] = Vg[(size_t)j0 * 32 + i2];
        }
        __syncthreads();

        // S = Q K^T * scale  — packed over d (horizontal add at end)
        ull s2[4][4];
#pragma unroll
        for (int i = 0; i < 4; i++)
#pragma unroll
            for (int j = 0; j < 4; j++) s2[i][j] = 0ull;

#pragma unroll 8
        for (int d2 = 0; d2 < 32; d2++) {
            ull qa2[4], kb2[4];
#pragma unroll
            for (int i = 0; i < 4; i++) {
                const float2 v = *(const float2*)&Qs[(sr + i) * FA_STRIDE + 2 * d2];
                qa2[i] = pack2(v.x, v.y);
            }
#pragma unroll
            for (int j = 0; j < 4; j++) {
                const float2 v = *(const float2*)&Ks[(sc + j) * FA_STRIDE + 2 * d2];
                kb2[j] = pack2(v.x, v.y);
            }
#pragma unroll
            for (int i = 0; i < 4; i++)
#pragma unroll
                for (int j = 0; j < 4; j++)
                    s2[i][j] = fma2(qa2[i], kb2[j], s2[i][j]);
        }
#pragma unroll
        for (int i = 0; i < 4; i++)
#pragma unroll
            for (int j = 0; j < 4; j++) {
                const float2 v = unpack2(s2[i][j]);
                Ss[(sr + i) * FA_STRIDE + sc + j] = (v.x + v.y) * 0.125f;
            }
        __syncthreads();

        // online softmax, one thread per row
        if (tid < 64) {
            const int r = tid;
            const float mo = rowm[r];
            float mx = mo;
#pragma unroll 8
            for (int c = 0; c < 64; c++) mx = fmaxf(mx, Ss[r * FA_STRIDE + c]);
            float sum = 0.f;
#pragma unroll 8
            for (int c = 0; c < 64; c++) {
                const float p = __expf(Ss[r * FA_STRIDE + c] - mx);
                Ss[r * FA_STRIDE + c] = p;
                sum += p;
            }
            const float fct = __expf(mo - mx);
            rowl[r] = rowl[r] * fct + sum;
            rowm[r] = mx;
            rowf[r] = fct;
        }
        __syncthreads();

        // P*V — packed over output-column pairs; P broadcast+dup
        ull t2[4][2];
#pragma unroll
        for (int i = 0; i < 4; i++) { t2[i][0] = 0ull; t2[i][1] = 0ull; }

#pragma unroll 8
        for (int c = 0; c < 64; c++) {
            const float2 v0 = *(const float2*)&Vs[c * FA_STRIDE + sc];
            const float2 v1 = *(const float2*)&Vs[c * FA_STRIDE + sc + 2];
            const ull vb0 = pack2(v0.x, v0.y);
            const ull vb1 = pack2(v1.x, v1.y);
#pragma unroll
            for (int i = 0; i < 4; i++) {
                const ull pa = dup2(Ss[(sr + i) * FA_STRIDE + c]);
                t2[i][0] = fma2(pa, vb0, t2[i][0]);
                t2[i][1] = fma2(pa, vb1, t2[i][1]);
            }
        }

        float fi[4];
#pragma unroll
        for (int i = 0; i < 4; i++) fi[i] = rowf[sr + i];
#pragma unroll
        for (int i = 0; i < 4; i++) {
            const float2 a = unpack2(t2[i][0]);
            const float2 b = unpack2(t2[i][1]);
            o[i][0] = o[i][0] * fi[i] + a.x;
            o[i][1] = o[i][1] * fi[i] + a.y;
            o[i][2] = o[i][2] * fi[i] + b.x;
            o[i][3] = o[i][3] * fi[i] + b.y;
        }
    }

    // finalize: divide by l, write attn output in [B,T, h*D+d] layout
    float li[4];
#pragma unroll
    for (int i = 0; i < 4; i++) li[i] = 1.f / rowl[sr + i];

    const int b = bh >> 4;
    const int h = bh & 15;
#pragma unroll
    for (int i = 0; i < 4; i++) {
        const int t = q0 + sr + i;
        float* dst = g_attn + ((size_t)(b * T_ + t)) * E_ + h * D_ + sc;
#pragma unroll
        for (int j = 0; j < 4; j++) dst[j] = o[i][j] * li[i];
    }
}

// ---------------------------------------------------------------------------
extern "C" void kernel_launch(void* const* d_in, const int* in_sizes, int n_in,
                              void* d_out, int out_size)
{
    const float* query     = (const float*)d_in[0];
    const float* positions = (const float*)d_in[1];
    const float* in_w      = (const float*)d_in[2];
    const float* in_b      = (const float*)d_in[3];
    const float* out_w     = (const float*)d_in[4];
    const float* out_b     = (const float*)d_in[5];
    const float* freqs     = (const float*)d_in[6];
    float* out = (float*)d_out;

    cudaFuncSetAttribute(flash_kernel,
                         cudaFuncAttributeMaxDynamicSharedMemorySize,
                         FA_SMEM_FLOATS * (int)sizeof(float));

    // 1) QKV projection, scattered head-major
    gemm_kernel<<<dim3(N3_ / 128, M_ / 128), 256>>>(query, in_w, in_b,
                                                    nullptr, N3_, E_, 1);
    // 2) rotary on Q and K
    rotary_kernel<<<(B_ * H_ * T_ * F_) / 256, 256>>>(positions, freqs);
    // 3) attention
    flash_kernel<<<dim3(T_ / 64, B_ * H_), 256,
                   FA_SMEM_FLOATS * (int)sizeof(float)>>>();
    // 4) output projection
    gemm_kernel<<<dim3(E_ / 128, M_ / 128), 256>>>(nullptr, out_w, out_b,
                                                   out, E_, E_, 2);
}

// round 6
// speedup vs baseline: 1.2063x; 1.2063x over previous
#include <cuda_runtime.h>
#include <math.h>
#include <stdint.h>

#define B_  4
#define T_  2048
#define E_  1024
#define H_  16
#define D_  64
#define F_  32
#define M_  (B_*T_)     // 8192
#define N3_ (3*E_)      // 3072

// Scratch (device globals; no allocation allowed)
__device__ float g_q[B_*H_*T_*D_];
__device__ float g_k[B_*H_*T_*D_];
__device__ float g_v[B_*H_*T_*D_];
__device__ float g_attn[M_*E_];

// ---------------------------------------------------------------------------
// TF32 helpers.  cvt.rna.tf32.f32 destination is .b32 (use "=r", NOT "=f").
// The tf32 bit-pattern is a valid fp32 (low mantissa bits zeroed), so the
// residual is computed via __uint_as_float.
// ---------------------------------------------------------------------------
__device__ __forceinline__ uint32_t f2tf32(float x) {
    uint32_t r;
    asm("cvt.rna.tf32.f32 %0, %1;" : "=r"(r) : "f"(x));
    return r;
}
__device__ __forceinline__ void split_tf32(float x, uint32_t& hi, uint32_t& lo) {
    hi = f2tf32(x);
    lo = f2tf32(x - __uint_as_float(hi));
}
__device__ __forceinline__ void mma_tf32(float* d, const uint32_t* a, const uint32_t* b) {
    asm volatile(
        "mma.sync.aligned.m16n8k8.row.col.f32.tf32.tf32.f32 "
        "{%0,%1,%2,%3}, {%4,%5,%6,%7}, {%8,%9}, {%0,%1,%2,%3};"
        : "+f"(d[0]), "+f"(d[1]), "+f"(d[2]), "+f"(d[3])
        : "r"(a[0]), "r"(a[1]), "r"(a[2]), "r"(a[3]), "r"(b[0]), "r"(b[1]));
}

// ===========================================================================
// Split-TF32 GEMM-NT: C[m,n] = sum_k A[m,k]*W[n,k] + bias[n]  (3-pass mma.sync)
//   mode 1: A = query, scatter C into g_q/g_k/g_v head-major layout
//   mode 2: A = g_attn, C = plain row-major output
// 128x128 C tile, BK=32, 512 threads (16 warps, 2x8 grid, 64x16 warp tiles).
// Smem: A_hi/A_lo/B_hi/B_lo (tf32 bit patterns), stride 36 (conflict-free).
// ===========================================================================
#define SMS 36
#define GEMM_SMEM_WORDS (4 * 128 * SMS)

__global__ __launch_bounds__(512)
void tc_gemm(const float* __restrict__ A_in, const float* __restrict__ W,
             const float* __restrict__ bias, float* __restrict__ C,
             int N, int K, int mode)
{
    extern __shared__ uint32_t smu[];
    uint32_t* Ah = smu;
    uint32_t* Al = smu + 128 * SMS;
    uint32_t* Bh = smu + 2 * 128 * SMS;
    uint32_t* Bl = smu + 3 * 128 * SMS;

    const float* A = (mode == 2) ? g_attn : A_in;

    const int tid  = threadIdx.x;
    const int lane = tid & 31;
    const int warp = tid >> 5;
    const int row0 = blockIdx.y * 128;
    const int col0 = blockIdx.x * 128;

    const int wm = (warp >> 3) * 64;   // warp m-offset (0 or 64)
    const int wn = (warp & 7) * 16;    // warp n-offset (0..112)
    const int g  = lane >> 2;          // group id 0..7
    const int tg = lane & 3;           // thread-in-group 0..3

    float acc[4][2][4];
#pragma unroll
    for (int mt = 0; mt < 4; mt++)
#pragma unroll
        for (int nt = 0; nt < 2; nt++)
#pragma unroll
            for (int i = 0; i < 4; i++) acc[mt][nt][i] = 0.f;

    // gmem load mapping: 2 float4 per thread per matrix per chunk
    const int lr0 = tid >> 3;          // rows 0..63
    const int lr1 = (tid + 512) >> 3;  // rows 64..127
    const int lc4 = (tid & 7) * 4;     // col within chunk
    const float* Ap0 = A + (size_t)(row0 + lr0) * K + lc4;
    const float* Ap1 = A + (size_t)(row0 + lr1) * K + lc4;
    const float* Wp0 = W + (size_t)(col0 + lr0) * K + lc4;
    const float* Wp1 = W + (size_t)(col0 + lr1) * K + lc4;

    float4 ra0 = *(const float4*)Ap0, ra1 = *(const float4*)Ap1;
    float4 rw0 = *(const float4*)Wp0, rw1 = *(const float4*)Wp1;

    const int nch = K / 32;
    for (int c = 0; c < nch; c++) {
        __syncthreads();   // previous compute done reading smem

        // split fp32 -> hi/lo tf32 bit-patterns and store
        {
            uint4 h, l;
            split_tf32(ra0.x, h.x, l.x); split_tf32(ra0.y, h.y, l.y);
            split_tf32(ra0.z, h.z, l.z); split_tf32(ra0.w, h.w, l.w);
            *(uint4*)&Ah[lr0 * SMS + lc4] = h; *(uint4*)&Al[lr0 * SMS + lc4] = l;
            split_tf32(ra1.x, h.x, l.x); split_tf32(ra1.y, h.y, l.y);
            split_tf32(ra1.z, h.z, l.z); split_tf32(ra1.w, h.w, l.w);
            *(uint4*)&Ah[lr1 * SMS + lc4] = h; *(uint4*)&Al[lr1 * SMS + lc4] = l;
            split_tf32(rw0.x, h.x, l.x); split_tf32(rw0.y, h.y, l.y);
            split_tf32(rw0.z, h.z, l.z); split_tf32(rw0.w, h.w, l.w);
            *(uint4*)&Bh[lr0 * SMS + lc4] = h; *(uint4*)&Bl[lr0 * SMS + lc4] = l;
            split_tf32(rw1.x, h.x, l.x); split_tf32(rw1.y, h.y, l.y);
            split_tf32(rw1.z, h.z, l.z); split_tf32(rw1.w, h.w, l.w);
            *(uint4*)&Bh[lr1 * SMS + lc4] = h; *(uint4*)&Bl[lr1 * SMS + lc4] = l;
        }
        __syncthreads();

        // prefetch next chunk (overlaps MMA below)
        if (c + 1 < nch) {
            const int ko = (c + 1) * 32;
            ra0 = *(const float4*)(Ap0 + ko); ra1 = *(const float4*)(Ap1 + ko);
            rw0 = *(const float4*)(Wp0 + ko); rw1 = *(const float4*)(Wp1 + ko);
        }

#pragma unroll
        for (int k8 = 0; k8 < 32; k8 += 8) {
            // B fragments (2 n-tiles), hi and lo
            uint32_t bh[2][2], bl[2][2];
#pragma unroll
            for (int nt = 0; nt < 2; nt++) {
                const int n = wn + nt * 8 + g;
                const int kk = k8 + tg;
                bh[nt][0] = Bh[n * SMS + kk];
                bh[nt][1] = Bh[n * SMS + kk + 4];
                bl[nt][0] = Bl[n * SMS + kk];
                bl[nt][1] = Bl[n * SMS + kk + 4];
            }
#pragma unroll
            for (int mt = 0; mt < 4; mt++) {
                const int m = wm + mt * 16;
                const int kk = k8 + tg;
                uint32_t ah[4], al[4];
                ah[0] = Ah[(m + g) * SMS + kk];
                ah[1] = Ah[(m + g + 8) * SMS + kk];
                ah[2] = Ah[(m + g) * SMS + kk + 4];
                ah[3] = Ah[(m + g + 8) * SMS + kk + 4];
                al[0] = Al[(m + g) * SMS + kk];
                al[1] = Al[(m + g + 8) * SMS + kk];
                al[2] = Al[(m + g) * SMS + kk + 4];
                al[3] = Al[(m + g + 8) * SMS + kk + 4];
#pragma unroll
                for (int nt = 0; nt < 2; nt++) {
                    mma_tf32(acc[mt][nt], ah, bh[nt]);
                    mma_tf32(acc[mt][nt], ah, bl[nt]);
                    mma_tf32(acc[mt][nt], al, bh[nt]);
                }
            }
        }
    }

    // -------- epilogue --------
#pragma unroll
    for (int mt = 0; mt < 4; mt++) {
#pragma unroll
        for (int nt = 0; nt < 2; nt++) {
#pragma unroll
            for (int half = 0; half < 2; half++) {
                const int m = row0 + wm + mt * 16 + g + half * 8;
                const int n = col0 + wn + nt * 8 + 2 * tg;
                const float vx = acc[mt][nt][2 * half]     + bias[n];
                const float vy = acc[mt][nt][2 * half + 1] + bias[n + 1];
                if (mode == 1) {
                    const int bb = m >> 11, t = m & 2047;
                    const int sec = n >> 10;
                    const int nn = n & 1023;
                    const int h = nn >> 6, d = nn & 63;
                    float* dst = ((sec == 0) ? g_q : (sec == 1) ? g_k : g_v)
                                 + ((size_t)(bb * H_ + h) * T_ + t) * D_ + d;
                    dst[0] = vx; dst[1] = vy;
                } else {
                    float* dst = C + (size_t)m * N + n;
                    dst[0] = vx; dst[1] = vy;
                }
            }
        }
    }
}

// ---------------------------------------------------------------------------
// Rotary: one thread per (b,h,t,f). cos/sin shared between Q and K.
// ---------------------------------------------------------------------------
__global__ __launch_bounds__(256)
void rotary_kernel(const float* __restrict__ pos, const float* __restrict__ freqs)
{
    const int idx = blockIdx.x * blockDim.x + threadIdx.x;
    const int f = idx & 31;
    const int t = (idx >> 5) & 2047;
    const int h = (idx >> 16) & 15;
    const int b = idx >> 20;

    const float* p  = pos   + ((size_t)b * T_ + t) * 3;
    const float* fr = freqs + ((size_t)h * F_ + f) * 3;
    const float ang = p[0] * fr[0] + p[1] * fr[1] + p[2] * fr[2];
    float s, c;
    sincosf(ang, &s, &c);

    const size_t base = ((size_t)(b * H_ + h) * T_ + t) * D_ + 2 * f;
    const float q0 = g_q[base], q1 = g_q[base + 1];
    g_q[base]     = q0 * c - q1 * s;
    g_q[base + 1] = q0 * s + q1 * c;
    const float k0 = g_k[base], k1 = g_k[base + 1];
    g_k[base]     = k0 * c - k1 * s;
    g_k[base + 1] = k0 * s + k1 * c;
}

// ---------------------------------------------------------------------------
// Flash attention, fp32 SIMT (R1 known-good version).
// ---------------------------------------------------------------------------
#define FA_SMEM_FLOATS (4 * 64 * 65 + 3 * 64)

__global__ __launch_bounds__(256)
void flash_kernel()
{
    extern __shared__ float sm[];
    float* Qs   = sm;                 // 64 x 65
    float* Ks   = sm + 4160;
    float* Vs   = sm + 8320;
    float* Ss   = sm + 12480;
    float* rowm = sm + 16640;         // 64
    float* rowl = rowm + 64;
    float* rowf = rowl + 64;

    const int tid = threadIdx.x;
    const int bh  = blockIdx.y;
    const int q0  = blockIdx.x * 64;

    const float* Qg = g_q + ((size_t)bh * T_ + q0) * D_;
    const float* Kg = g_k + (size_t)bh * T_ * D_;
    const float* Vg = g_v + (size_t)bh * T_ * D_;

    for (int i = tid; i < 4096; i += 256) {
        const int r = i >> 6, c = i & 63;
        Qs[r * 65 + c] = Qg[i];
    }
    if (tid < 64) { rowm[tid] = -INFINITY; rowl[tid] = 0.f; }

    const int sr = (tid >> 4) << 2;
    const int sc = (tid & 15) << 2;

    float o[4][4];
#pragma unroll
    for (int i = 0; i < 4; i++)
#pragma unroll
        for (int j = 0; j < 4; j++) o[i][j] = 0.f;

    for (int j0 = 0; j0 < T_; j0 += 64) {
        __syncthreads();
        for (int i = tid; i < 4096; i += 256) {
            const int r = i >> 6, c = i & 63;
            Ks[r * 65 + c] = Kg[(size_t)j0 * 64 + i];
            Vs[r * 65 + c] = Vg[(size_t)j0 * 64 + i];
        }
        __syncthreads();

        float s[4][4];
#pragma unroll
        for (int i = 0; i < 4; i++)
#pragma unroll
            for (int j = 0; j < 4; j++) s[i][j] = 0.f;

#pragma unroll 8
        for (int d = 0; d < 64; d++) {
            float qa[4], kb[4];
#pragma unroll
            for (int i = 0; i < 4; i++) qa[i] = Qs[(sr + i) * 65 + d];
#pragma unroll
            for (int j = 0; j < 4; j++) kb[j] = Ks[(sc + j) * 65 + d];
#pragma unroll
            for (int i = 0; i < 4; i++)
#pragma unroll
                for (int j = 0; j < 4; j++)
                    s[i][j] += qa[i] * kb[j];
        }
#pragma unroll
        for (int i = 0; i < 4; i++)
#pragma unroll
            for (int j = 0; j < 4; j++)
                Ss[(sr + i) * 65 + sc + j] = s[i][j] * 0.125f;
        __syncthreads();

        if (tid < 64) {
            const int r = tid;
            const float mo = rowm[r];
            float mx = mo;
#pragma unroll 8
            for (int c = 0; c < 64; c++) mx = fmaxf(mx, Ss[r * 65 + c]);
            float sum = 0.f;
#pragma unroll 8
            for (int c = 0; c < 64; c++) {
                const float p = __expf(Ss[r * 65 + c] - mx);
                Ss[r * 65 + c] = p;
                sum += p;
            }
            const float fct = __expf(mo - mx);
            rowl[r] = rowl[r] * fct + sum;
            rowm[r] = mx;
            rowf[r] = fct;
        }
        __syncthreads();

        float fi[4];
#pragma unroll
        for (int i = 0; i < 4; i++) fi[i] = rowf[sr + i];
#pragma unroll
        for (int i = 0; i < 4; i++)
#pragma unroll
            for (int j = 0; j < 4; j++) o[i][j] *= fi[i];

#pragma unroll 8
        for (int c = 0; c < 64; c++) {
            float vb[4], pa[4];
#pragma unroll
            for (int j = 0; j < 4; j++) vb[j] = Vs[c * 65 + sc + j];
#pragma unroll
            for (int i = 0; i < 4; i++) pa[i] = Ss[(sr + i) * 65 + c];
#pragma unroll
            for (int i = 0; i < 4; i++)
#pragma unroll
                for (int j = 0; j < 4; j++)
                    o[i][j] += pa[i] * vb[j];
        }
    }

    float li[4];
#pragma unroll
    for (int i = 0; i < 4; i++) li[i] = 1.f / rowl[sr + i];

    const int b = bh >> 4;
    const int h = bh & 15;
#pragma unroll
    for (int i = 0; i < 4; i++) {
        const int t = q0 + sr + i;
        float* dst = g_attn + ((size_t)(b * T_ + t)) * E_ + h * D_ + sc;
#pragma unroll
        for (int j = 0; j < 4; j++) dst[j] = o[i][j] * li[i];
    }
}

// ---------------------------------------------------------------------------
extern "C" void kernel_launch(void* const* d_in, const int* in_sizes, int n_in,
                              void* d_out, int out_size)
{
    const float* query     = (const float*)d_in[0];
    const float* positions = (const float*)d_in[1];
    const float* in_w      = (const float*)d_in[2];
    const float* in_b      = (const float*)d_in[3];
    const float* out_w     = (const float*)d_in[4];
    const float* out_b     = (const float*)d_in[5];
    const float* freqs     = (const float*)d_in[6];
    float* out = (float*)d_out;

    cudaFuncSetAttribute(tc_gemm,
                         cudaFuncAttributeMaxDynamicSharedMemorySize,
                         GEMM_SMEM_WORDS * (int)sizeof(uint32_t));
    cudaFuncSetAttribute(flash_kernel,
                         cudaFuncAttributeMaxDynamicSharedMemorySize,
                         FA_SMEM_FLOATS * (int)sizeof(float));

    // 1) QKV projection (split-TF32 mma.sync), scattered head-major
    tc_gemm<<<dim3(N3_ / 128, M_ / 128), 512,
              GEMM_SMEM_WORDS * (int)sizeof(uint32_t)>>>(query, in_w, in_b,
                                                         nullptr, N3_, E_, 1);
    // 2) rotary on Q and K
    rotary_kernel<<<(B_ * H_ * T_ * F_) / 256, 256>>>(positions, freqs);
    // 3) attention (fp32 SIMT)
    flash_kernel<<<dim3(T_ / 64, B_ * H_), 256,
                   FA_SMEM_FLOATS * (int)sizeof(float)>>>();
    // 4) output projection (split-TF32 mma.sync)
    tc_gemm<<<dim3(E_ / 128, M_ / 128), 512,
              GEMM_SMEM_WORDS * (int)sizeof(uint32_t)>>>(nullptr, out_w, out_b,
                                                         out, E_, E_, 2);
}

// round 8
// speedup vs baseline: 1.7504x; 1.4511x over previous
// R7: byte-identical resubmission of R6 (infra "container failed twice" — per
// R4/R5 precedent, resubmit unchanged to surface the true error, if any).
#include <cuda_runtime.h>
#include <cuda_bf16.h>
#include <math.h>
#include <stdint.h>

#define B_  4
#define T_  2048
#define E_  1024
#define H_  16
#define D_  64
#define F_  32
#define M_  (B_*T_)     // 8192
#define N3_ (3*E_)      // 3072

// Scratch (device globals; no allocation allowed)
__device__ float g_q[B_*H_*T_*D_];
__device__ float g_k[B_*H_*T_*D_];
__device__ float g_v[B_*H_*T_*D_];
__device__ float g_attn[M_*E_];

// ---------------------------------------------------------------------------
// TF32 helpers (validated R5)
// ---------------------------------------------------------------------------
__device__ __forceinline__ uint32_t f2tf32(float x) {
    uint32_t r;
    asm("cvt.rna.tf32.f32 %0, %1;" : "=r"(r) : "f"(x));
    return r;
}
__device__ __forceinline__ void split_tf32(float x, uint32_t& hi, uint32_t& lo) {
    hi = f2tf32(x);
    lo = f2tf32(x - __uint_as_float(hi));
}
__device__ __forceinline__ void mma_tf32(float* d, const uint32_t* a, const uint32_t* b) {
    asm volatile(
        "mma.sync.aligned.m16n8k8.row.col.f32.tf32.tf32.f32 "
        "{%0,%1,%2,%3}, {%4,%5,%6,%7}, {%8,%9}, {%0,%1,%2,%3};"
        : "+f"(d[0]), "+f"(d[1]), "+f"(d[2]), "+f"(d[3])
        : "r"(a[0]), "r"(a[1]), "r"(a[2]), "r"(a[3]), "r"(b[0]), "r"(b[1]));
}

// ---------------------------------------------------------------------------
// BF16 helpers (flash)
// ---------------------------------------------------------------------------
__device__ __forceinline__ void mma_bf16(float* d, const uint32_t* a, const uint32_t* b) {
    asm volatile(
        "mma.sync.aligned.m16n8k16.row.col.f32.bf16.bf16.f32 "
        "{%0,%1,%2,%3}, {%4,%5,%6,%7}, {%8,%9}, {%0,%1,%2,%3};"
        : "+f"(d[0]), "+f"(d[1]), "+f"(d[2]), "+f"(d[3])
        : "r"(a[0]), "r"(a[1]), "r"(a[2]), "r"(a[3]), "r"(b[0]), "r"(b[1]));
}
// split x into hi+lo bf16, pack (x0,x1) -> words (x0 in low half)
__device__ __forceinline__ void split_pack(float x0, float x1, uint32_t& hi, uint32_t& lo) {
    __nv_bfloat162 h, l;
    h.x = __float2bfloat16(x0); h.y = __float2bfloat16(x1);
    l.x = __float2bfloat16(x0 - __bfloat162float(h.x));
    l.y = __float2bfloat16(x1 - __bfloat162float(h.y));
    hi = *(uint32_t*)&h; lo = *(uint32_t*)&l;
}
// fast exp on FMA/ALU pipes (no MUFU): rel err ~2e-6, valid for x <= 0
__device__ __forceinline__ float fexp(float x) {
    float t = fmaxf(x * 1.4426950408889634f, -126.0f);
    float tn = t + 12582912.0f;           // round t to nearest int in mantissa
    float nf = tn - 12582912.0f;
    float f  = t - nf;                    // f in [-0.5, 0.5]
    float p  = 0.0013333558f;
    p = fmaf(p, f, 0.0096181291f);
    p = fmaf(p, f, 0.0555041087f);
    p = fmaf(p, f, 0.2402265069f);
    p = fmaf(p, f, 0.6931471806f);
    p = fmaf(p, f, 1.0f);
    uint32_t eb = (__float_as_uint(tn) << 23) + 0x3F800000u;  // 2^n bits
    return p * __uint_as_float(eb);
}

// ===========================================================================
// Split-TF32 GEMM-NT (validated R5, unchanged)
// ===========================================================================
#define SMS 36
#define GEMM_SMEM_WORDS (4 * 128 * SMS)

__global__ __launch_bounds__(512)
void tc_gemm(const float* __restrict__ A_in, const float* __restrict__ W,
             const float* __restrict__ bias, float* __restrict__ C,
             int N, int K, int mode)
{
    extern __shared__ uint32_t smu[];
    uint32_t* Ah = smu;
    uint32_t* Al = smu + 128 * SMS;
    uint32_t* Bh = smu + 2 * 128 * SMS;
    uint32_t* Bl = smu + 3 * 128 * SMS;

    const float* A = (mode == 2) ? g_attn : A_in;

    const int tid  = threadIdx.x;
    const int lane = tid & 31;
    const int warp = tid >> 5;
    const int row0 = blockIdx.y * 128;
    const int col0 = blockIdx.x * 128;

    const int wm = (warp >> 3) * 64;
    const int wn = (warp & 7) * 16;
    const int g  = lane >> 2;
    const int tg = lane & 3;

    float acc[4][2][4];
#pragma unroll
    for (int mt = 0; mt < 4; mt++)
#pragma unroll
        for (int nt = 0; nt < 2; nt++)
#pragma unroll
            for (int i = 0; i < 4; i++) acc[mt][nt][i] = 0.f;

    const int lr0 = tid >> 3;
    const int lr1 = (tid + 512) >> 3;
    const int lc4 = (tid & 7) * 4;
    const float* Ap0 = A + (size_t)(row0 + lr0) * K + lc4;
    const float* Ap1 = A + (size_t)(row0 + lr1) * K + lc4;
    const float* Wp0 = W + (size_t)(col0 + lr0) * K + lc4;
    const float* Wp1 = W + (size_t)(col0 + lr1) * K + lc4;

    float4 ra0 = *(const float4*)Ap0, ra1 = *(const float4*)Ap1;
    float4 rw0 = *(const float4*)Wp0, rw1 = *(const float4*)Wp1;

    const int nch = K / 32;
    for (int c = 0; c < nch; c++) {
        __syncthreads();
        {
            uint4 h, l;
            split_tf32(ra0.x, h.x, l.x); split_tf32(ra0.y, h.y, l.y);
            split_tf32(ra0.z, h.z, l.z); split_tf32(ra0.w, h.w, l.w);
            *(uint4*)&Ah[lr0 * SMS + lc4] = h; *(uint4*)&Al[lr0 * SMS + lc4] = l;
            split_tf32(ra1.x, h.x, l.x); split_tf32(ra1.y, h.y, l.y);
            split_tf32(ra1.z, h.z, l.z); split_tf32(ra1.w, h.w, l.w);
            *(uint4*)&Ah[lr1 * SMS + lc4] = h; *(uint4*)&Al[lr1 * SMS + lc4] = l;
            split_tf32(rw0.x, h.x, l.x); split_tf32(rw0.y, h.y, l.y);
            split_tf32(rw0.z, h.z, l.z); split_tf32(rw0.w, h.w, l.w);
            *(uint4*)&Bh[lr0 * SMS + lc4] = h; *(uint4*)&Bl[lr0 * SMS + lc4] = l;
            split_tf32(rw1.x, h.x, l.x); split_tf32(rw1.y, h.y, l.y);
            split_tf32(rw1.z, h.z, l.z); split_tf32(rw1.w, h.w, l.w);
            *(uint4*)&Bh[lr1 * SMS + lc4] = h; *(uint4*)&Bl[lr1 * SMS + lc4] = l;
        }
        __syncthreads();

        if (c + 1 < nch) {
            const int ko = (c + 1) * 32;
            ra0 = *(const float4*)(Ap0 + ko); ra1 = *(const float4*)(Ap1 + ko);
            rw0 = *(const float4*)(Wp0 + ko); rw1 = *(const float4*)(Wp1 + ko);
        }

#pragma unroll
        for (int k8 = 0; k8 < 32; k8 += 8) {
            uint32_t bh[2][2], bl[2][2];
#pragma unroll
            for (int nt = 0; nt < 2; nt++) {
                const int n = wn + nt * 8 + g;
                const int kk = k8 + tg;
                bh[nt][0] = Bh[n * SMS + kk];
                bh[nt][1] = Bh[n * SMS + kk + 4];
                bl[nt][0] = Bl[n * SMS + kk];
                bl[nt][1] = Bl[n * SMS + kk + 4];
            }
#pragma unroll
            for (int mt = 0; mt < 4; mt++) {
                const int m = wm + mt * 16;
                const int kk = k8 + tg;
                uint32_t ah[4], al[4];
                ah[0] = Ah[(m + g) * SMS + kk];
                ah[1] = Ah[(m + g + 8) * SMS + kk];
                ah[2] = Ah[(m + g) * SMS + kk + 4];
                ah[3] = Ah[(m + g + 8) * SMS + kk + 4];
                al[0] = Al[(m + g) * SMS + kk];
                al[1] = Al[(m + g + 8) * SMS + kk];
                al[2] = Al[(m + g) * SMS + kk + 4];
                al[3] = Al[(m + g + 8) * SMS + kk + 4];
#pragma unroll
                for (int nt = 0; nt < 2; nt++) {
                    mma_tf32(acc[mt][nt], ah, bh[nt]);
                    mma_tf32(acc[mt][nt], ah, bl[nt]);
                    mma_tf32(acc[mt][nt], al, bh[nt]);
                }
            }
        }
    }

#pragma unroll
    for (int mt = 0; mt < 4; mt++) {
#pragma unroll
        for (int nt = 0; nt < 2; nt++) {
#pragma unroll
            for (int half = 0; half < 2; half++) {
                const int m = row0 + wm + mt * 16 + g + half * 8;
                const int n = col0 + wn + nt * 8 + 2 * tg;
                const float vx = acc[mt][nt][2 * half]     + bias[n];
                const float vy = acc[mt][nt][2 * half + 1] + bias[n + 1];
                if (mode == 1) {
                    const int bb = m >> 11, t = m & 2047;
                    const int sec = n >> 10;
                    const int nn = n & 1023;
                    const int h = nn >> 6, d = nn & 63;
                    float* dst = ((sec == 0) ? g_q : (sec == 1) ? g_k : g_v)
                                 + ((size_t)(bb * H_ + h) * T_ + t) * D_ + d;
                    dst[0] = vx; dst[1] = vy;
                } else {
                    float* dst = C + (size_t)m * N + n;
                    dst[0] = vx; dst[1] = vy;
                }
            }
        }
    }
}

// ---------------------------------------------------------------------------
// Rotary (unchanged)
// ---------------------------------------------------------------------------
__global__ __launch_bounds__(256)
void rotary_kernel(const float* __restrict__ pos, const float* __restrict__ freqs)
{
    const int idx = blockIdx.x * blockDim.x + threadIdx.x;
    const int f = idx & 31;
    const int t = (idx >> 5) & 2047;
    const int h = (idx >> 16) & 15;
    const int b = idx >> 20;

    const float* p  = pos   + ((size_t)b * T_ + t) * 3;
    const float* fr = freqs + ((size_t)h * F_ + f) * 3;
    const float ang = p[0] * fr[0] + p[1] * fr[1] + p[2] * fr[2];
    float s, c;
    sincosf(ang, &s, &c);

    const size_t base = ((size_t)(b * H_ + h) * T_ + t) * D_ + 2 * f;
    const float q0 = g_q[base], q1 = g_q[base + 1];
    g_q[base]     = q0 * c - q1 * s;
    g_q[base + 1] = q0 * s + q1 * c;
    const float k0 = g_k[base], k1 = g_k[base + 1];
    g_k[base]     = k0 * c - k1 * s;
    g_k[base + 1] = k0 * s + k1 * c;
}

// ===========================================================================
// Tensor-core flash attention: split-BF16 3-pass mma + polynomial exp.
// Block = one (b,h) x 64-query tile; 256 threads (8 warps).
// Planes are bf16x2 words packed over the contraction dim, stride 36 words.
// P*V computed as O^T = V^T * P^T (V transposed into smem at load).
// ===========================================================================
#define FW   36                          // word stride of bf16x2 planes
#define SSW  66                          // float stride of Ss
#define QH_  0
#define QL_  (64*FW)
#define KH_  (2*64*FW)
#define KL_  (3*64*FW)
#define VH_  (4*64*FW)
#define VL_  (5*64*FW)
#define PH_  (6*64*FW)
#define PL_  (7*64*FW)
#define SS_  (8*64*FW)                   // fp32 scores, 64 x 66
#define RM_  (SS_ + 64*SSW)
#define RL_  (RM_ + 64)
#define RF_  (RL_ + 64)
#define FAB_WORDS (RF_ + 64)

__global__ __launch_bounds__(256)
void flash_kernel()
{
    extern __shared__ uint32_t sw[];
    float* sf = (float*)sw;

    const int tid  = threadIdx.x;
    const int lane = tid & 31;
    const int warp = tid >> 5;
    const int bh   = blockIdx.y;
    const int q0   = blockIdx.x * 64;

    const float* Qg = g_q + ((size_t)bh * T_ + q0) * D_;
    const float* Kg = g_k + (size_t)bh * T_ * D_;
    const float* Vg = g_v + (size_t)bh * T_ * D_;

    const int g  = lane >> 2;          // 0..7
    const int tg = lane & 3;           // 0..3
    const int mw = (warp >> 1) * 16;   // warp row tile (q for S, d for O)
    const int nw = (warp & 1) * 32;    // warp col tile (key for S, q for O)

    // ---- load Q planes (once) ----
#pragma unroll
    for (int it = 0; it < 8; it++) {
        const int idx = tid + it * 256;        // 2048 words
        const int r = idx >> 5, dp = idx & 31;
        const float2 v = *(const float2*)(Qg + r * 64 + 2 * dp);
        uint32_t hi, lo;
        split_pack(v.x, v.y, hi, lo);
        sw[QH_ + r * FW + dp] = hi;
        sw[QL_ + r * FW + dp] = lo;
    }
    if (tid < 64) { sf[RM_ + tid] = -INFINITY; sf[RL_ + tid] = 0.f; }

    float oc[4][4];                    // O^T accumulator (d rows, q cols)
#pragma unroll
    for (int j = 0; j < 4; j++)
#pragma unroll
        for (int i = 0; i < 4; i++) oc[j][i] = 0.f;

    for (int j0 = 0; j0 < T_; j0 += 64) {
        __syncthreads();               // prev-iter consumers done

        // ---- K planes ----
#pragma unroll
        for (int it = 0; it < 8; it++) {
            const int idx = tid + it * 256;
            const int r = idx >> 5, dp = idx & 31;
            const float2 v = *(const float2*)(Kg + (size_t)(j0 + r) * 64 + 2 * dp);
            uint32_t hi, lo;
            split_pack(v.x, v.y, hi, lo);
            sw[KH_ + r * FW + dp] = hi;
            sw[KL_ + r * FW + dp] = lo;
        }
        // ---- V transposed planes: Vt[d][keypair] ----
        {
            const int kp = warp * 4 + (lane >> 3);    // 0..31
#pragma unroll
            for (int it = 0; it < 8; it++) {
                const int d = (lane & 7) + 8 * it;    // 0..63
                const float v0 = Vg[(size_t)(j0 + 2 * kp) * 64 + d];
                const float v1 = Vg[(size_t)(j0 + 2 * kp + 1) * 64 + d];
                uint32_t hi, lo;
                split_pack(v0, v1, hi, lo);
                sw[VH_ + d * FW + kp] = hi;
                sw[VL_ + d * FW + kp] = lo;
            }
        }
        __syncthreads();

        // ---- S = Q K^T (3-pass split bf16) ----
        float sc[4][4];
#pragma unroll
        for (int j = 0; j < 4; j++)
#pragma unroll
            for (int i = 0; i < 4; i++) sc[j][i] = 0.f;

#pragma unroll
        for (int ks = 0; ks < 4; ks++) {
            const int kw = 8 * ks + tg;
            uint32_t ah[4], al[4];
            ah[0] = sw[QH_ + (mw + g) * FW + kw];
            ah[1] = sw[QH_ + (mw + g + 8) * FW + kw];
            ah[2] = sw[QH_ + (mw + g) * FW + kw + 4];
            ah[3] = sw[QH_ + (mw + g + 8) * FW + kw + 4];
            al[0] = sw[QL_ + (mw + g) * FW + kw];
            al[1] = sw[QL_ + (mw + g + 8) * FW + kw];
            al[2] = sw[QL_ + (mw + g) * FW + kw + 4];
            al[3] = sw[QL_ + (mw + g + 8) * FW + kw + 4];
#pragma unroll
            for (int j = 0; j < 4; j++) {
                const int br = (nw + 8 * j + g) * FW + kw;
                uint32_t bh2[2] = { sw[KH_ + br], sw[KH_ + br + 4] };
                uint32_t bl2[2] = { sw[KL_ + br], sw[KL_ + br + 4] };
                mma_bf16(sc[j], ah, bh2);
                mma_bf16(sc[j], ah, bl2);
                mma_bf16(sc[j], al, bh2);
            }
        }
#pragma unroll
        for (int j = 0; j < 4; j++) {
            const int col = nw + 8 * j + 2 * tg;
            *(float2*)&sf[SS_ + (mw + g) * SSW + col] =
                make_float2(sc[j][0] * 0.125f, sc[j][1] * 0.125f);
            *(float2*)&sf[SS_ + (mw + g + 8) * SSW + col] =
                make_float2(sc[j][2] * 0.125f, sc[j][3] * 0.125f);
        }
        __syncthreads();

        // ---- softmax: 4 threads per row, FMA-pipe exp ----
        {
            const int r = tid >> 2, sub = tid & 3;
            const float* row = &sf[SS_ + r * SSW + sub * 16];
            float vb[16];
            float mx = row[0];
#pragma unroll
            for (int i = 0; i < 16; i++) { vb[i] = row[i]; mx = fmaxf(mx, vb[i]); }
            mx = fmaxf(mx, __shfl_xor_sync(0xffffffffu, mx, 1));
            mx = fmaxf(mx, __shfl_xor_sync(0xffffffffu, mx, 2));
            const float mo = sf[RM_ + r];
            const float mn = fmaxf(mo, mx);
            float sum = 0.f;
            uint32_t hw8[8], lw8[8];
#pragma unroll
            for (int i = 0; i < 8; i++) {
                const float p0 = fexp(vb[2 * i] - mn);
                const float p1 = fexp(vb[2 * i + 1] - mn);
                sum += p0 + p1;
                split_pack(p0, p1, hw8[i], lw8[i]);
            }
            sum += __shfl_xor_sync(0xffffffffu, sum, 1);
            sum += __shfl_xor_sync(0xffffffffu, sum, 2);
            if (sub == 0) {
                const float fct = fexp(mo - mn);
                sf[RL_ + r] = sf[RL_ + r] * fct + sum;
                sf[RM_ + r] = mn;
                sf[RF_ + r] = fct;
            }
#pragma unroll
            for (int i = 0; i < 8; i++) {
                sw[PH_ + r * FW + sub * 8 + i] = hw8[i];
                sw[PL_ + r * FW + sub * 8 + i] = lw8[i];
            }
        }
        __syncthreads();

        // ---- O^T = V^T P^T : rescale then 3-pass accumulate ----
#pragma unroll
        for (int j = 0; j < 4; j++) {
            const float f0 = sf[RF_ + nw + 8 * j + 2 * tg];
            const float f1 = sf[RF_ + nw + 8 * j + 2 * tg + 1];
            oc[j][0] *= f0; oc[j][1] *= f1; oc[j][2] *= f0; oc[j][3] *= f1;
        }
#pragma unroll
        for (int ks = 0; ks < 4; ks++) {
            const int kw = 8 * ks + tg;
            uint32_t ah[4], al[4];
            ah[0] = sw[VH_ + (mw + g) * FW + kw];
            ah[1] = sw[VH_ + (mw + g + 8) * FW + kw];
            ah[2] = sw[VH_ + (mw + g) * FW + kw + 4];
            ah[3] = sw[VH_ + (mw + g + 8) * FW + kw + 4];
            al[0] = sw[VL_ + (mw + g) * FW + kw];
            al[1] = sw[VL_ + (mw + g + 8) * FW + kw];
            al[2] = sw[VL_ + (mw + g) * FW + kw + 4];
            al[3] = sw[VL_ + (mw + g + 8) * FW + kw + 4];
#pragma unroll
            for (int j = 0; j < 4; j++) {
                const int br = (nw + 8 * j + g) * FW + kw;
                uint32_t bh2[2] = { sw[PH_ + br], sw[PH_ + br + 4] };
                uint32_t bl2[2] = { sw[PL_ + br], sw[PL_ + br + 4] };
                mma_bf16(oc[j], ah, bh2);
                mma_bf16(oc[j], ah, bl2);
                mma_bf16(oc[j], al, bh2);
            }
        }
    }

    // ---- finalize: O^T[d][q] / l[q] -> g_attn[b, t=q0+q, h*64+d] ----
    const int bb = bh >> 4, hh = bh & 15;
#pragma unroll
    for (int j = 0; j < 4; j++) {
        const int qq = nw + 8 * j + 2 * tg;
        const float li0 = 1.f / sf[RL_ + qq];
        const float li1 = 1.f / sf[RL_ + qq + 1];
        const int d = mw + g;
        float* d0 = g_attn + ((size_t)(bb * T_ + q0 + qq)) * E_ + hh * 64 + d;
        float* d1 = g_attn + ((size_t)(bb * T_ + q0 + qq + 1)) * E_ + hh * 64 + d;
        d0[0] = oc[j][0] * li0;
        d1[0] = oc[j][1] * li1;
        d0[8] = oc[j][2] * li0;
        d1[8] = oc[j][3] * li1;
    }
}

// ---------------------------------------------------------------------------
extern "C" void kernel_launch(void* const* d_in, const int* in_sizes, int n_in,
                              void* d_out, int out_size)
{
    const float* query     = (const float*)d_in[0];
    const float* positions = (const float*)d_in[1];
    const float* in_w      = (const float*)d_in[2];
    const float* in_b      = (const float*)d_in[3];
    const float* out_w     = (const float*)d_in[4];
    const float* out_b     = (const float*)d_in[5];
    const float* freqs     = (const float*)d_in[6];
    float* out = (float*)d_out;

    cudaFuncSetAttribute(tc_gemm,
                         cudaFuncAttributeMaxDynamicSharedMemorySize,
                         GEMM_SMEM_WORDS * (int)sizeof(uint32_t));
    cudaFuncSetAttribute(flash_kernel,
                         cudaFuncAttributeMaxDynamicSharedMemorySize,
                         FAB_WORDS * (int)sizeof(uint32_t));

    // 1) QKV projection (split-TF32 mma.sync), scattered head-major
    tc_gemm<<<dim3(N3_ / 128, M_ / 128), 512,
              GEMM_SMEM_WORDS * (int)sizeof(uint32_t)>>>(query, in_w, in_b,
                                                         nullptr, N3_, E_, 1);
    // 2) rotary on Q and K
    rotary_kernel<<<(B_ * H_ * T_ * F_) / 256, 256>>>(positions, freqs);
    // 3) attention (split-BF16 mma.sync + poly exp)
    flash_kernel<<<dim3(T_ / 64, B_ * H_), 256,
                   FAB_WORDS * (int)sizeof(uint32_t)>>>();
    // 4) output projection (split-TF32 mma.sync)
    tc_gemm<<<dim3(E_ / 128, M_ / 128), 512,
              GEMM_SMEM_WORDS * (int)sizeof(uint32_t)>>>(nullptr, out_w, out_b,
                                                         out, E_, E_, 2);
}

// round 10
// speedup vs baseline: 1.9677x; 1.1241x over previous
// R9: byte-identical resubmission of R8 (infra "container failed twice" — per
// R0/R4/R6 precedent, resubmit unchanged to disambiguate flake vs real error).
#include <cuda_runtime.h>
#include <cuda_bf16.h>
#include <math.h>
#include <stdint.h>

#define B_  4
#define T_  2048
#define E_  1024
#define H_  16
#define D_  64
#define F_  32
#define M_  (B_*T_)     // 8192
#define N3_ (3*E_)      // 3072

// Scratch (device globals; no allocation allowed)
__device__ float g_q[B_*H_*T_*D_];
__device__ float g_k[B_*H_*T_*D_];
__device__ float g_v[B_*H_*T_*D_];
__device__ float g_attn[M_*E_];

// ---------------------------------------------------------------------------
// BF16 helpers
// ---------------------------------------------------------------------------
__device__ __forceinline__ void mma_bf16(float* d, const uint32_t* a, const uint32_t* b) {
    asm volatile(
        "mma.sync.aligned.m16n8k16.row.col.f32.bf16.bf16.f32 "
        "{%0,%1,%2,%3}, {%4,%5,%6,%7}, {%8,%9}, {%0,%1,%2,%3};"
        : "+f"(d[0]), "+f"(d[1]), "+f"(d[2]), "+f"(d[3])
        : "r"(a[0]), "r"(a[1]), "r"(a[2]), "r"(a[3]), "r"(b[0]), "r"(b[1]));
}
// split x into hi+lo bf16, pack (x0,x1) -> words (x0 in low half)
__device__ __forceinline__ void split_pack(float x0, float x1, uint32_t& hi, uint32_t& lo) {
    __nv_bfloat162 h, l;
    h.x = __float2bfloat16(x0); h.y = __float2bfloat16(x1);
    l.x = __float2bfloat16(x0 - __bfloat162float(h.x));
    l.y = __float2bfloat16(x1 - __bfloat162float(h.y));
    hi = *(uint32_t*)&h; lo = *(uint32_t*)&l;
}
// fast exp on FMA/ALU pipes (no MUFU): rel err ~2e-6, valid for x <= 0
__device__ __forceinline__ float fexp(float x) {
    float t = fmaxf(x * 1.4426950408889634f, -126.0f);
    float tn = t + 12582912.0f;           // round t to nearest int in mantissa
    float nf = tn - 12582912.0f;
    float f  = t - nf;                    // f in [-0.5, 0.5]
    float p  = 0.0013333558f;
    p = fmaf(p, f, 0.0096181291f);
    p = fmaf(p, f, 0.0555041087f);
    p = fmaf(p, f, 0.2402265069f);
    p = fmaf(p, f, 0.6931471806f);
    p = fmaf(p, f, 1.0f);
    uint32_t eb = (__float_as_uint(tn) << 23) + 0x3F800000u;  // 2^n bits
    return p * __uint_as_float(eb);
}

// ===========================================================================
// Split-BF16 GEMM-NT: C[m,n] = sum_k A[m,k]*W[n,k] + bias[n]
// 3-pass hi/lo, mma m16n8k16. 128x128 C tile, BK=32, 512 threads
// (16 warps, 2x8 grid, 64x16 warp tiles). Planes: bf16x2 words over K,
// word stride 18.
//   mode 1: A = query, scatter C into g_q/g_k/g_v head-major layout
//   mode 2: A = g_attn, C = plain row-major output
// ===========================================================================
#define SMSB 18
#define GEMM_SMEM_WORDS (4 * 128 * SMSB)

__global__ __launch_bounds__(512)
void tc_gemm(const float* __restrict__ A_in, const float* __restrict__ W,
             const float* __restrict__ bias, float* __restrict__ C,
             int N, int K, int mode)
{
    extern __shared__ uint32_t smu[];
    uint32_t* Ah = smu;
    uint32_t* Al = smu + 128 * SMSB;
    uint32_t* Bh = smu + 2 * 128 * SMSB;
    uint32_t* Bl = smu + 3 * 128 * SMSB;

    const float* A = (mode == 2) ? g_attn : A_in;

    const int tid  = threadIdx.x;
    const int lane = tid & 31;
    const int warp = tid >> 5;
    const int row0 = blockIdx.y * 128;
    const int col0 = blockIdx.x * 128;

    const int wm = (warp >> 3) * 64;   // warp m-offset (0 or 64)
    const int wn = (warp & 7) * 16;    // warp n-offset (0..112)
    const int g  = lane >> 2;          // 0..7
    const int tg = lane & 3;           // 0..3

    float acc[4][2][4];
#pragma unroll
    for (int mt = 0; mt < 4; mt++)
#pragma unroll
        for (int nt = 0; nt < 2; nt++)
#pragma unroll
            for (int i = 0; i < 4; i++) acc[mt][nt][i] = 0.f;

    // gmem load mapping: 2 float4 per thread per matrix per chunk
    const int lr0 = tid >> 3;          // rows 0..63
    const int lr1 = (tid + 512) >> 3;  // rows 64..127
    const int lc4 = (tid & 7) * 4;     // float col within chunk (0..28)
    const int w0  = (tid & 7) * 2;     // word col within chunk (0..14)
    const float* Ap0 = A + (size_t)(row0 + lr0) * K + lc4;
    const float* Ap1 = A + (size_t)(row0 + lr1) * K + lc4;
    const float* Wp0 = W + (size_t)(col0 + lr0) * K + lc4;
    const float* Wp1 = W + (size_t)(col0 + lr1) * K + lc4;

    float4 ra0 = *(const float4*)Ap0, ra1 = *(const float4*)Ap1;
    float4 rw0 = *(const float4*)Wp0, rw1 = *(const float4*)Wp1;

    const int nch = K / 32;
    for (int c = 0; c < nch; c++) {
        __syncthreads();   // previous compute done reading smem

        // split fp32 -> packed bf16 hi/lo planes
        {
            uint32_t h0, l0, h1, l1;
            split_pack(ra0.x, ra0.y, h0, l0); split_pack(ra0.z, ra0.w, h1, l1);
            *(uint2*)&Ah[lr0 * SMSB + w0] = make_uint2(h0, h1);
            *(uint2*)&Al[lr0 * SMSB + w0] = make_uint2(l0, l1);
            split_pack(ra1.x, ra1.y, h0, l0); split_pack(ra1.z, ra1.w, h1, l1);
            *(uint2*)&Ah[lr1 * SMSB + w0] = make_uint2(h0, h1);
            *(uint2*)&Al[lr1 * SMSB + w0] = make_uint2(l0, l1);
            split_pack(rw0.x, rw0.y, h0, l0); split_pack(rw0.z, rw0.w, h1, l1);
            *(uint2*)&Bh[lr0 * SMSB + w0] = make_uint2(h0, h1);
            *(uint2*)&Bl[lr0 * SMSB + w0] = make_uint2(l0, l1);
            split_pack(rw1.x, rw1.y, h0, l0); split_pack(rw1.z, rw1.w, h1, l1);
            *(uint2*)&Bh[lr1 * SMSB + w0] = make_uint2(h0, h1);
            *(uint2*)&Bl[lr1 * SMSB + w0] = make_uint2(l0, l1);
        }
        __syncthreads();

        // prefetch next chunk (overlaps MMA below)
        if (c + 1 < nch) {
            const int ko = (c + 1) * 32;
            ra0 = *(const float4*)(Ap0 + ko); ra1 = *(const float4*)(Ap1 + ko);
            rw0 = *(const float4*)(Wp0 + ko); rw1 = *(const float4*)(Wp1 + ko);
        }

        // 2 k16-steps per chunk (word offsets 0 and 8)
#pragma unroll
        for (int ks = 0; ks < 2; ks++) {
            const int kw = 8 * ks + tg;
            uint32_t bh2[2][2], bl2[2][2];
#pragma unroll
            for (int nt = 0; nt < 2; nt++) {
                const int n = wn + nt * 8 + g;
                bh2[nt][0] = Bh[n * SMSB + kw];
                bh2[nt][1] = Bh[n * SMSB + kw + 4];
                bl2[nt][0] = Bl[n * SMSB + kw];
                bl2[nt][1] = Bl[n * SMSB + kw + 4];
            }
#pragma unroll
            for (int mt = 0; mt < 4; mt++) {
                const int m = wm + mt * 16;
                uint32_t ah[4], al[4];
                ah[0] = Ah[(m + g) * SMSB + kw];
                ah[1] = Ah[(m + g + 8) * SMSB + kw];
                ah[2] = Ah[(m + g) * SMSB + kw + 4];
                ah[3] = Ah[(m + g + 8) * SMSB + kw + 4];
                al[0] = Al[(m + g) * SMSB + kw];
                al[1] = Al[(m + g + 8) * SMSB + kw];
                al[2] = Al[(m + g) * SMSB + kw + 4];
                al[3] = Al[(m + g + 8) * SMSB + kw + 4];
#pragma unroll
                for (int nt = 0; nt < 2; nt++) {
                    mma_bf16(acc[mt][nt], ah, bh2[nt]);
                    mma_bf16(acc[mt][nt], ah, bl2[nt]);
                    mma_bf16(acc[mt][nt], al, bh2[nt]);
                }
            }
        }
    }

    // -------- epilogue (C layout identical to m16n8k8) --------
#pragma unroll
    for (int mt = 0; mt < 4; mt++) {
#pragma unroll
        for (int nt = 0; nt < 2; nt++) {
#pragma unroll
            for (int half = 0; half < 2; half++) {
                const int m = row0 + wm + mt * 16 + g + half * 8;
                const int n = col0 + wn + nt * 8 + 2 * tg;
                const float vx = acc[mt][nt][2 * half]     + bias[n];
                const float vy = acc[mt][nt][2 * half + 1] + bias[n + 1];
                if (mode == 1) {
                    const int bb = m >> 11, t = m & 2047;
                    const int sec = n >> 10;
                    const int nn = n & 1023;
                    const int h = nn >> 6, d = nn & 63;
                    float* dst = ((sec == 0) ? g_q : (sec == 1) ? g_k : g_v)
                                 + ((size_t)(bb * H_ + h) * T_ + t) * D_ + d;
                    dst[0] = vx; dst[1] = vy;
                } else {
                    float* dst = C + (size_t)m * N + n;
                    dst[0] = vx; dst[1] = vy;
                }
            }
        }
    }
}

// ---------------------------------------------------------------------------
// Rotary (unchanged)
// ---------------------------------------------------------------------------
__global__ __launch_bounds__(256)
void rotary_kernel(const float* __restrict__ pos, const float* __restrict__ freqs)
{
    const int idx = blockIdx.x * blockDim.x + threadIdx.x;
    const int f = idx & 31;
    const int t = (idx >> 5) & 2047;
    const int h = (idx >> 16) & 15;
    const int b = idx >> 20;

    const float* p  = pos   + ((size_t)b * T_ + t) * 3;
    const float* fr = freqs + ((size_t)h * F_ + f) * 3;
    const float ang = p[0] * fr[0] + p[1] * fr[1] + p[2] * fr[2];
    float s, c;
    sincosf(ang, &s, &c);

    const size_t base = ((size_t)(b * H_ + h) * T_ + t) * D_ + 2 * f;
    const float q0 = g_q[base], q1 = g_q[base + 1];
    g_q[base]     = q0 * c - q1 * s;
    g_q[base + 1] = q0 * s + q1 * c;
    const float k0 = g_k[base], k1 = g_k[base + 1];
    g_k[base]     = k0 * c - k1 * s;
    g_k[base + 1] = k0 * s + k1 * c;
}

// ===========================================================================
// Tensor-core flash attention (validated R7, unchanged)
// ===========================================================================
#define FW   36                          // word stride of bf16x2 planes
#define SSW  66                          // float stride of Ss
#define QH_  0
#define QL_  (64*FW)
#define KH_  (2*64*FW)
#define KL_  (3*64*FW)
#define VH_  (4*64*FW)
#define VL_  (5*64*FW)
#define PH_  (6*64*FW)
#define PL_  (7*64*FW)
#define SS_  (8*64*FW)                   // fp32 scores, 64 x 66
#define RM_  (SS_ + 64*SSW)
#define RL_  (RM_ + 64)
#define RF_  (RL_ + 64)
#define FAB_WORDS (RF_ + 64)

__global__ __launch_bounds__(256)
void flash_kernel()
{
    extern __shared__ uint32_t sw[];
    float* sf = (float*)sw;

    const int tid  = threadIdx.x;
    const int lane = tid & 31;
    const int warp = tid >> 5;
    const int bh   = blockIdx.y;
    const int q0   = blockIdx.x * 64;

    const float* Qg = g_q + ((size_t)bh * T_ + q0) * D_;
    const float* Kg = g_k + (size_t)bh * T_ * D_;
    const float* Vg = g_v + (size_t)bh * T_ * D_;

    const int g  = lane >> 2;          // 0..7
    const int tg = lane & 3;           // 0..3
    const int mw = (warp >> 1) * 16;   // warp row tile (q for S, d for O)
    const int nw = (warp & 1) * 32;    // warp col tile (key for S, q for O)

    // ---- load Q planes (once) ----
#pragma unroll
    for (int it = 0; it < 8; it++) {
        const int idx = tid + it * 256;        // 2048 words
        const int r = idx >> 5, dp = idx & 31;
        const float2 v = *(const float2*)(Qg + r * 64 + 2 * dp);
        uint32_t hi, lo;
        split_pack(v.x, v.y, hi, lo);
        sw[QH_ + r * FW + dp] = hi;
        sw[QL_ + r * FW + dp] = lo;
    }
    if (tid < 64) { sf[RM_ + tid] = -INFINITY; sf[RL_ + tid] = 0.f; }

    float oc[4][4];                    // O^T accumulator (d rows, q cols)
#pragma unroll
    for (int j = 0; j < 4; j++)
#pragma unroll
        for (int i = 0; i < 4; i++) oc[j][i] = 0.f;

    for (int j0 = 0; j0 < T_; j0 += 64) {
        __syncthreads();               // prev-iter consumers done

        // ---- K planes ----
#pragma unroll
        for (int it = 0; it < 8; it++) {
            const int idx = tid + it * 256;
            const int r = idx >> 5, dp = idx & 31;
            const float2 v = *(const float2*)(Kg + (size_t)(j0 + r) * 64 + 2 * dp);
            uint32_t hi, lo;
            split_pack(v.x, v.y, hi, lo);
            sw[KH_ + r * FW + dp] = hi;
            sw[KL_ + r * FW + dp] = lo;
        }
        // ---- V transposed planes: Vt[d][keypair] ----
        {
            const int kp = warp * 4 + (lane >> 3);    // 0..31
#pragma unroll
            for (int it = 0; it < 8; it++) {
                const int d = (lane & 7) + 8 * it;    // 0..63
                const float v0 = Vg[(size_t)(j0 + 2 * kp) * 64 + d];
                const float v1 = Vg[(size_t)(j0 + 2 * kp + 1) * 64 + d];
                uint32_t hi, lo;
                split_pack(v0, v1, hi, lo);
                sw[VH_ + d * FW + kp] = hi;
                sw[VL_ + d * FW + kp] = lo;
            }
        }
        __syncthreads();

        // ---- S = Q K^T (3-pass split bf16) ----
        float sc[4][4];
#pragma unroll
        for (int j = 0; j < 4; j++)
#pragma unroll
            for (int i = 0; i < 4; i++) sc[j][i] = 0.f;

#pragma unroll
        for (int ks = 0; ks < 4; ks++) {
            const int kw = 8 * ks + tg;
            uint32_t ah[4], al[4];
            ah[0] = sw[QH_ + (mw + g) * FW + kw];
            ah[1] = sw[QH_ + (mw + g + 8) * FW + kw];
            ah[2] = sw[QH_ + (mw + g) * FW + kw + 4];
            ah[3] = sw[QH_ + (mw + g + 8) * FW + kw + 4];
            al[0] = sw[QL_ + (mw + g) * FW + kw];
            al[1] = sw[QL_ + (mw + g + 8) * FW + kw];
            al[2] = sw[QL_ + (mw + g) * FW + kw + 4];
            al[3] = sw[QL_ + (mw + g + 8) * FW + kw + 4];
#pragma unroll
            for (int j = 0; j < 4; j++) {
                const int br = (nw + 8 * j + g) * FW + kw;
                uint32_t bh2[2] = { sw[KH_ + br], sw[KH_ + br + 4] };
                uint32_t bl2[2] = { sw[KL_ + br], sw[KL_ + br + 4] };
                mma_bf16(sc[j], ah, bh2);
                mma_bf16(sc[j], ah, bl2);
                mma_bf16(sc[j], al, bh2);
            }
        }
#pragma unroll
        for (int j = 0; j < 4; j++) {
            const int col = nw + 8 * j + 2 * tg;
            *(float2*)&sf[SS_ + (mw + g) * SSW + col] =
                make_float2(sc[j][0] * 0.125f, sc[j][1] * 0.125f);
            *(float2*)&sf[SS_ + (mw + g + 8) * SSW + col] =
                make_float2(sc[j][2] * 0.125f, sc[j][3] * 0.125f);
        }
        __syncthreads();

        // ---- softmax: 4 threads per row, FMA-pipe exp ----
        {
            const int r = tid >> 2, sub = tid & 3;
            const float* row = &sf[SS_ + r * SSW + sub * 16];
            float vb[16];
            float mx = row[0];
#pragma unroll
            for (int i = 0; i < 16; i++) { vb[i] = row[i]; mx = fmaxf(mx, vb[i]); }
            mx = fmaxf(mx, __shfl_xor_sync(0xffffffffu, mx, 1));
            mx = fmaxf(mx, __shfl_xor_sync(0xffffffffu, mx, 2));
            const float mo = sf[RM_ + r];
            const float mn = fmaxf(mo, mx);
            float sum = 0.f;
            uint32_t hw8[8], lw8[8];
#pragma unroll
            for (int i = 0; i < 8; i++) {
                const float p0 = fexp(vb[2 * i] - mn);
                const float p1 = fexp(vb[2 * i + 1] - mn);
                sum += p0 + p1;
                split_pack(p0, p1, hw8[i], lw8[i]);
            }
            sum += __shfl_xor_sync(0xffffffffu, sum, 1);
            sum += __shfl_xor_sync(0xffffffffu, sum, 2);
            if (sub == 0) {
                const float fct = fexp(mo - mn);
                sf[RL_ + r] = sf[RL_ + r] * fct + sum;
                sf[RM_ + r] = mn;
                sf[RF_ + r] = fct;
            }
#pragma unroll
            for (int i = 0; i < 8; i++) {
                sw[PH_ + r * FW + sub * 8 + i] = hw8[i];
                sw[PL_ + r * FW + sub * 8 + i] = lw8[i];
            }
        }
        __syncthreads();

        // ---- O^T = V^T P^T : rescale then 3-pass accumulate ----
#pragma unroll
        for (int j = 0; j < 4; j++) {
            const float f0 = sf[RF_ + nw + 8 * j + 2 * tg];
            const float f1 = sf[RF_ + nw + 8 * j + 2 * tg + 1];
            oc[j][0] *= f0; oc[j][1] *= f1; oc[j][2] *= f0; oc[j][3] *= f1;
        }
#pragma unroll
        for (int ks = 0; ks < 4; ks++) {
            const int kw = 8 * ks + tg;
            uint32_t ah[4], al[4];
            ah[0] = sw[VH_ + (mw + g) * FW + kw];
            ah[1] = sw[VH_ + (mw + g + 8) * FW + kw];
            ah[2] = sw[VH_ + (mw + g) * FW + kw + 4];
            ah[3] = sw[VH_ + (mw + g + 8) * FW + kw + 4];
            al[0] = sw[VL_ + (mw + g) * FW + kw];
            al[1] = sw[VL_ + (mw + g + 8) * FW + kw];
            al[2] = sw[VL_ + (mw + g) * FW + kw + 4];
            al[3] = sw[VL_ + (mw + g + 8) * FW + kw + 4];
#pragma unroll
            for (int j = 0; j < 4; j++) {
                const int br = (nw + 8 * j + g) * FW + kw;
                uint32_t bh2[2] = { sw[PH_ + br], sw[PH_ + br + 4] };
                uint32_t bl2[2] = { sw[PL_ + br], sw[PL_ + br + 4] };
                mma_bf16(oc[j], ah, bh2);
                mma_bf16(oc[j], ah, bl2);
                mma_bf16(oc[j], al, bh2);
            }
        }
    }

    // ---- finalize: O^T[d][q] / l[q] -> g_attn[b, t=q0+q, h*64+d] ----
    const int bb = bh >> 4, hh = bh & 15;
#pragma unroll
    for (int j = 0; j < 4; j++) {
        const int qq = nw + 8 * j + 2 * tg;
        const float li0 = 1.f / sf[RL_ + qq];
        const float li1 = 1.f / sf[RL_ + qq + 1];
        const int d = mw + g;
        float* d0 = g_attn + ((size_t)(bb * T_ + q0 + qq)) * E_ + hh * 64 + d;
        float* d1 = g_attn + ((size_t)(bb * T_ + q0 + qq + 1)) * E_ + hh * 64 + d;
        d0[0] = oc[j][0] * li0;
        d1[0] = oc[j][1] * li1;
        d0[8] = oc[j][2] * li0;
        d1[8] = oc[j][3] * li1;
    }
}

// ---------------------------------------------------------------------------
extern "C" void kernel_launch(void* const* d_in, const int* in_sizes, int n_in,
                              void* d_out, int out_size)
{
    const float* query     = (const float*)d_in[0];
    const float* positions = (const float*)d_in[1];
    const float* in_w      = (const float*)d_in[2];
    const float* in_b      = (const float*)d_in[3];
    const float* out_w     = (const float*)d_in[4];
    const float* out_b     = (const float*)d_in[5];
    const float* freqs     = (const float*)d_in[6];
    float* out = (float*)d_out;

    cudaFuncSetAttribute(tc_gemm,
                         cudaFuncAttributeMaxDynamicSharedMemorySize,
                         GEMM_SMEM_WORDS * (int)sizeof(uint32_t));
    cudaFuncSetAttribute(flash_kernel,
                         cudaFuncAttributeMaxDynamicSharedMemorySize,
                         FAB_WORDS * (int)sizeof(uint32_t));

    // 1) QKV projection (split-BF16 mma.sync), scattered head-major
    tc_gemm<<<dim3(N3_ / 128, M_ / 128), 512,
              GEMM_SMEM_WORDS * (int)sizeof(uint32_t)>>>(query, in_w, in_b,
                                                         nullptr, N3_, E_, 1);
    // 2) rotary on Q and K
    rotary_kernel<<<(B_ * H_ * T_ * F_) / 256, 256>>>(positions, freqs);
    // 3) attention (split-BF16 mma.sync + poly exp)
    flash_kernel<<<dim3(T_ / 64, B_ * H_), 256,
                   FAB_WORDS * (int)sizeof(uint32_t)>>>();
    // 4) output projection (split-BF16 mma.sync)
    tc_gemm<<<dim3(E_ / 128, M_ / 128), 512,
              GEMM_SMEM_WORDS * (int)sizeof(uint32_t)>>>(nullptr, out_w, out_b,
                                                         out, E_, E_, 2);
}

// round 11
// speedup vs baseline: 2.3519x; 1.1952x over previous
#include <cuda_runtime.h>
#include <cuda_bf16.h>
#include <math.h>
#include <stdint.h>

#define B_  4
#define T_  2048
#define E_  1024
#define H_  16
#define D_  64
#define F_  32
#define M_  (B_*T_)     // 8192
#define N3_ (3*E_)      // 3072

// Scratch (device globals; no allocation allowed)
__device__ float g_q[B_*H_*T_*D_];
__device__ float g_k[B_*H_*T_*D_];
__device__ float g_v[B_*H_*T_*D_];
__device__ float g_attn[M_*E_];

// ---------------------------------------------------------------------------
// helpers
// ---------------------------------------------------------------------------
__device__ __forceinline__ uint32_t smem_u32(const void* p) {
    uint32_t a;
    asm("{ .reg .u64 t; cvta.to.shared.u64 t, %1; cvt.u32.u64 %0, t; }"
        : "=r"(a) : "l"(p));
    return a;
}
__device__ __forceinline__ void mma_bf16(float* d, const uint32_t* a, const uint32_t* b) {
    asm volatile(
        "mma.sync.aligned.m16n8k16.row.col.f32.bf16.bf16.f32 "
        "{%0,%1,%2,%3}, {%4,%5,%6,%7}, {%8,%9}, {%0,%1,%2,%3};"
        : "+f"(d[0]), "+f"(d[1]), "+f"(d[2]), "+f"(d[3])
        : "r"(a[0]), "r"(a[1]), "r"(a[2]), "r"(a[3]), "r"(b[0]), "r"(b[1]));
}
#define LDMX4(r, addr)                                                        \
    asm volatile("ldmatrix.sync.aligned.m8n8.x4.shared.b16 {%0,%1,%2,%3}, [%4];" \
        : "=r"((r)[0]), "=r"((r)[1]), "=r"((r)[2]), "=r"((r)[3]) : "r"(addr))
#define LDMX2(r, addr)                                                        \
    asm volatile("ldmatrix.sync.aligned.m8n8.x2.shared.b16 {%0,%1}, [%2];"    \
        : "=r"((r)[0]), "=r"((r)[1]) : "r"(addr))

// split x into hi+lo bf16, pack (x0,x1) -> words (x0 in low half)
__device__ __forceinline__ void split_pack(float x0, float x1, uint32_t& hi, uint32_t& lo) {
    __nv_bfloat162 h, l;
    h.x = __float2bfloat16(x0); h.y = __float2bfloat16(x1);
    l.x = __float2bfloat16(x0 - __bfloat162float(h.x));
    l.y = __float2bfloat16(x1 - __bfloat162float(h.y));
    hi = *(uint32_t*)&h; lo = *(uint32_t*)&l;
}
// fast exp on FMA/ALU pipes (no MUFU): rel err ~2e-6, valid for x <= 0
__device__ __forceinline__ float fexp(float x) {
    float t = fmaxf(x * 1.4426950408889634f, -126.0f);
    float tn = t + 12582912.0f;
    float nf = tn - 12582912.0f;
    float f  = t - nf;
    float p  = 0.0013333558f;
    p = fmaf(p, f, 0.0096181291f);
    p = fmaf(p, f, 0.0555041087f);
    p = fmaf(p, f, 0.2402265069f);
    p = fmaf(p, f, 0.6931471806f);
    p = fmaf(p, f, 1.0f);
    uint32_t eb = (__float_as_uint(tn) << 23) + 0x3F800000u;
    return p * __uint_as_float(eb);
}

// ===========================================================================
// Split-BF16 GEMM-NT, double-buffered + ldmatrix.
// C[m,n] = sum_k A[m,k]*W[n,k] + bias[n], 3-pass hi/lo, m16n8k16.
// 128x128 C tile, BK=32, 512 threads (16 warps, 2x8 grid, 64x16 warp tiles).
// Planes: bf16x2 words over K, word stride 20 (16B-aligned ldmatrix rows,
// banks 20r mod 32 -> all 32 banks once). Two buffers, 1 barrier per chunk.
//   mode 1: A = query, scatter C into g_q/g_k/g_v head-major layout
//   mode 2: A = g_attn, C = plain row-major output
// ===========================================================================
#define SMSB  20
#define PLANE (128 * SMSB)        // 2560 words
#define BUFW  (4 * PLANE)         // 10240 words per buffer
#define GEMM_SMEM_WORDS (2 * BUFW)

__global__ __launch_bounds__(512)
void tc_gemm(const float* __restrict__ A_in, const float* __restrict__ W,
             const float* __restrict__ bias, float* __restrict__ C,
             int N, int K, int mode)
{
    extern __shared__ uint32_t smu[];
    const uint32_t sb = smem_u32(smu);

    const float* A = (mode == 2) ? g_attn : A_in;

    const int tid  = threadIdx.x;
    const int lane = tid & 31;
    const int warp = tid >> 5;
    const int row0 = blockIdx.y * 128;
    const int col0 = blockIdx.x * 128;

    const int wm = (warp >> 3) * 64;   // warp m-offset (0 or 64)
    const int wn = (warp & 7) * 16;    // warp n-offset (0..112)

    float acc[4][2][4];
#pragma unroll
    for (int mt = 0; mt < 4; mt++)
#pragma unroll
        for (int nt = 0; nt < 2; nt++)
#pragma unroll
            for (int i = 0; i < 4; i++) acc[mt][nt][i] = 0.f;

    // ---- gmem load mapping: 2 float4 per thread per matrix per chunk ----
    const int lr0 = tid >> 3;          // rows 0..63
    const int lr1 = (tid + 512) >> 3;  // rows 64..127
    const int lc4 = (tid & 7) * 4;     // float col within chunk (0..28)
    const int w0  = (tid & 7) * 2;     // word col within chunk (0..14)
    const float* Ap0 = A + (size_t)(row0 + lr0) * K + lc4;
    const float* Ap1 = A + (size_t)(row0 + lr1) * K + lc4;
    const float* Wp0 = W + (size_t)(col0 + lr0) * K + lc4;
    const float* Wp1 = W + (size_t)(col0 + lr1) * K + lc4;

    // ---- ldmatrix per-lane addresses (byte offsets within a buffer) ----
    const int q  = lane >> 3;          // 0..3 (address group)
    const int rr = lane & 7;           // row within group
    // A x4: groups -> (rows +0/+8, words +0/+4): matrices a0..a3
    const uint32_t a_off = (uint32_t)(((q & 1) * 8 + rr) * SMSB + (q >> 1) * 4) * 4;
    // B x2: groups 0/1 -> words +0/+4 (lanes 16-31 mirror, ignored)
    const uint32_t b_off = (uint32_t)(rr * SMSB + (q & 1) * 4) * 4;

    const uint32_t ah_base = sb + (uint32_t)(wm * SMSB) * 4 + a_off;              // Ah plane
    const uint32_t al_base = ah_base + PLANE * 4;
    const uint32_t bh_base = sb + (2 * PLANE + wn * SMSB) * 4 + b_off;
    const uint32_t bl_base = bh_base + PLANE * 4;

    float4 ra0 = *(const float4*)Ap0, ra1 = *(const float4*)Ap1;
    float4 rw0 = *(const float4*)Wp0, rw1 = *(const float4*)Wp1;

    // ---- split/store helper (to buffer `buf`) ----
    auto store_chunk = [&](int buf) {
        uint32_t* Ah = smu + buf * BUFW;
        uint32_t* Al = Ah + PLANE;
        uint32_t* Bh = Al + PLANE;
        uint32_t* Bl = Bh + PLANE;
        uint32_t h0, l0, h1, l1;
        split_pack(ra0.x, ra0.y, h0, l0); split_pack(ra0.z, ra0.w, h1, l1);
        *(uint2*)&Ah[lr0 * SMSB + w0] = make_uint2(h0, h1);
        *(uint2*)&Al[lr0 * SMSB + w0] = make_uint2(l0, l1);
        split_pack(ra1.x, ra1.y, h0, l0); split_pack(ra1.z, ra1.w, h1, l1);
        *(uint2*)&Ah[lr1 * SMSB + w0] = make_uint2(h0, h1);
        *(uint2*)&Al[lr1 * SMSB + w0] = make_uint2(l0, l1);
        split_pack(rw0.x, rw0.y, h0, l0); split_pack(rw0.z, rw0.w, h1, l1);
        *(uint2*)&Bh[lr0 * SMSB + w0] = make_uint2(h0, h1);
        *(uint2*)&Bl[lr0 * SMSB + w0] = make_uint2(l0, l1);
        split_pack(rw1.x, rw1.y, h0, l0); split_pack(rw1.z, rw1.w, h1, l1);
        *(uint2*)&Bh[lr1 * SMSB + w0] = make_uint2(h0, h1);
        *(uint2*)&Bl[lr1 * SMSB + w0] = make_uint2(l0, l1);
    };

    // prologue: chunk 0 into buffer 0
    store_chunk(0);
    __syncthreads();

    const int nch = K / 32;
    for (int c = 0; c < nch; c++) {
        // prefetch gmem regs for chunk c+1 (overlaps mma below)
        if (c + 1 < nch) {
            const int ko = (c + 1) * 32;
            ra0 = *(const float4*)(Ap0 + ko); ra1 = *(const float4*)(Ap1 + ko);
            rw0 = *(const float4*)(Wp0 + ko); rw1 = *(const float4*)(Wp1 + ko);
        }

        // ---- mma phase on buffer c&1 ----
        const uint32_t bofs = (uint32_t)((c & 1) * BUFW) * 4;
#pragma unroll
        for (int ks = 0; ks < 2; ks++) {
            const uint32_t kb = bofs + ks * 32;   // 8 words per k16 step
            uint32_t bhf[2][2], blf[2][2];
#pragma unroll
            for (int nt = 0; nt < 2; nt++) {
                LDMX2(bhf[nt], bh_base + nt * 640 + kb);
                LDMX2(blf[nt], bl_base + nt * 640 + kb);
            }
#pragma unroll
            for (int mt = 0; mt < 4; mt++) {
                uint32_t ah[4], al[4];
                LDMX4(ah, ah_base + mt * 1280 + kb);
                LDMX4(al, al_base + mt * 1280 + kb);
#pragma unroll
                for (int nt = 0; nt < 2; nt++) {
                    mma_bf16(acc[mt][nt], ah, bhf[nt]);
                    mma_bf16(acc[mt][nt], ah, blf[nt]);
                    mma_bf16(acc[mt][nt], al, bhf[nt]);
                }
            }
        }

        // ---- store chunk c+1 to the other buffer ----
        if (c + 1 < nch) store_chunk((c + 1) & 1);
        __syncthreads();
    }

    // -------- epilogue --------
    const int g  = lane >> 2;
    const int tg = lane & 3;
#pragma unroll
    for (int mt = 0; mt < 4; mt++) {
#pragma unroll
        for (int nt = 0; nt < 2; nt++) {
#pragma unroll
            for (int half = 0; half < 2; half++) {
                const int m = row0 + wm + mt * 16 + g + half * 8;
                const int n = col0 + wn + nt * 8 + 2 * tg;
                const float vx = acc[mt][nt][2 * half]     + bias[n];
                const float vy = acc[mt][nt][2 * half + 1] + bias[n + 1];
                if (mode == 1) {
                    const int bb = m >> 11, t = m & 2047;
                    const int sec = n >> 10;
                    const int nn = n & 1023;
                    const int h = nn >> 6, d = nn & 63;
                    float* dst = ((sec == 0) ? g_q : (sec == 1) ? g_k : g_v)
                                 + ((size_t)(bb * H_ + h) * T_ + t) * D_ + d;
                    dst[0] = vx; dst[1] = vy;
                } else {
                    float* dst = C + (size_t)m * N + n;
                    dst[0] = vx; dst[1] = vy;
                }
            }
        }
    }
}

// ---------------------------------------------------------------------------
// Rotary (unchanged)
// ---------------------------------------------------------------------------
__global__ __launch_bounds__(256)
void rotary_kernel(const float* __restrict__ pos, const float* __restrict__ freqs)
{
    const int idx = blockIdx.x * blockDim.x + threadIdx.x;
    const int f = idx & 31;
    const int t = (idx >> 5) & 2047;
    const int h = (idx >> 16) & 15;
    const int b = idx >> 20;

    const float* p  = pos   + ((size_t)b * T_ + t) * 3;
    const float* fr = freqs + ((size_t)h * F_ + f) * 3;
    const float ang = p[0] * fr[0] + p[1] * fr[1] + p[2] * fr[2];
    float s, c;
    sincosf(ang, &s, &c);

    const size_t base = ((size_t)(b * H_ + h) * T_ + t) * D_ + 2 * f;
    const float q0 = g_q[base], q1 = g_q[base + 1];
    g_q[base]     = q0 * c - q1 * s;
    g_q[base + 1] = q0 * s + q1 * c;
    const float k0 = g_k[base], k1 = g_k[base + 1];
    g_k[base]     = k0 * c - k1 * s;
    g_k[base + 1] = k0 * s + k1 * c;
}

// ===========================================================================
// Tensor-core flash attention (validated R7, unchanged)
// ===========================================================================
#define FW   36                          // word stride of bf16x2 planes
#define SSW  66                          // float stride of Ss
#define QH_  0
#define QL_  (64*FW)
#define KH_  (2*64*FW)
#define KL_  (3*64*FW)
#define VH_  (4*64*FW)
#define VL_  (5*64*FW)
#define PH_  (6*64*FW)
#define PL_  (7*64*FW)
#define SS_  (8*64*FW)                   // fp32 scores, 64 x 66
#define RM_  (SS_ + 64*SSW)
#define RL_  (RM_ + 64)
#define RF_  (RL_ + 64)
#define FAB_WORDS (RF_ + 64)

__global__ __launch_bounds__(256)
void flash_kernel()
{
    extern __shared__ uint32_t sw[];
    float* sf = (float*)sw;

    const int tid  = threadIdx.x;
    const int lane = tid & 31;
    const int warp = tid >> 5;
    const int bh   = blockIdx.y;
    const int q0   = blockIdx.x * 64;

    const float* Qg = g_q + ((size_t)bh * T_ + q0) * D_;
    const float* Kg = g_k + (size_t)bh * T_ * D_;
    const float* Vg = g_v + (size_t)bh * T_ * D_;

    const int g  = lane >> 2;          // 0..7
    const int tg = lane & 3;           // 0..3
    const int mw = (warp >> 1) * 16;   // warp row tile (q for S, d for O)
    const int nw = (warp & 1) * 32;    // warp col tile (key for S, q for O)

    // ---- load Q planes (once) ----
#pragma unroll
    for (int it = 0; it < 8; it++) {
        const int idx = tid + it * 256;        // 2048 words
        const int r = idx >> 5, dp = idx & 31;
        const float2 v = *(const float2*)(Qg + r * 64 + 2 * dp);
        uint32_t hi, lo;
        split_pack(v.x, v.y, hi, lo);
        sw[QH_ + r * FW + dp] = hi;
        sw[QL_ + r * FW + dp] = lo;
    }
    if (tid < 64) { sf[RM_ + tid] = -INFINITY; sf[RL_ + tid] = 0.f; }

    float oc[4][4];                    // O^T accumulator (d rows, q cols)
#pragma unroll
    for (int j = 0; j < 4; j++)
#pragma unroll
        for (int i = 0; i < 4; i++) oc[j][i] = 0.f;

    for (int j0 = 0; j0 < T_; j0 += 64) {
        __syncthreads();               // prev-iter consumers done

        // ---- K planes ----
#pragma unroll
        for (int it = 0; it < 8; it++) {
            const int idx = tid + it * 256;
            const int r = idx >> 5, dp = idx & 31;
            const float2 v = *(const float2*)(Kg + (size_t)(j0 + r) * 64 + 2 * dp);
            uint32_t hi, lo;
            split_pack(v.x, v.y, hi, lo);
            sw[KH_ + r * FW + dp] = hi;
            sw[KL_ + r * FW + dp] = lo;
        }
        // ---- V transposed planes: Vt[d][keypair] ----
        {
            const int kp = warp * 4 + (lane >> 3);    // 0..31
#pragma unroll
            for (int it = 0; it < 8; it++) {
                const int d = (lane & 7) + 8 * it;    // 0..63
                const float v0 = Vg[(size_t)(j0 + 2 * kp) * 64 + d];
                const float v1 = Vg[(size_t)(j0 + 2 * kp + 1) * 64 + d];
                uint32_t hi, lo;
                split_pack(v0, v1, hi, lo);
                sw[VH_ + d * FW + kp] = hi;
                sw[VL_ + d * FW + kp] = lo;
            }
        }
        __syncthreads();

        // ---- S = Q K^T (3-pass split bf16) ----
        float sc[4][4];
#pragma unroll
        for (int j = 0; j < 4; j++)
#pragma unroll
            for (int i = 0; i < 4; i++) sc[j][i] = 0.f;

#pragma unroll
        for (int ks = 0; ks < 4; ks++) {
            const int kw = 8 * ks + tg;
            uint32_t ah[4], al[4];
            ah[0] = sw[QH_ + (mw + g) * FW + kw];
            ah[1] = sw[QH_ + (mw + g + 8) * FW + kw];
            ah[2] = sw[QH_ + (mw + g) * FW + kw + 4];
            ah[3] = sw[QH_ + (mw + g + 8) * FW + kw + 4];
            al[0] = sw[QL_ + (mw + g) * FW + kw];
            al[1] = sw[QL_ + (mw + g + 8) * FW + kw];
            al[2] = sw[QL_ + (mw + g) * FW + kw + 4];
            al[3] = sw[QL_ + (mw + g + 8) * FW + kw + 4];
#pragma unroll
            for (int j = 0; j < 4; j++) {
                const int br = (nw + 8 * j + g) * FW + kw;
                uint32_t bh2[2] = { sw[KH_ + br], sw[KH_ + br + 4] };
                uint32_t bl2[2] = { sw[KL_ + br], sw[KL_ + br + 4] };
                mma_bf16(sc[j], ah, bh2);
                mma_bf16(sc[j], ah, bl2);
                mma_bf16(sc[j], al, bh2);
            }
        }
#pragma unroll
        for (int j = 0; j < 4; j++) {
            const int col = nw + 8 * j + 2 * tg;
            *(float2*)&sf[SS_ + (mw + g) * SSW + col] =
                make_float2(sc[j][0] * 0.125f, sc[j][1] * 0.125f);
            *(float2*)&sf[SS_ + (mw + g + 8) * SSW + col] =
                make_float2(sc[j][2] * 0.125f, sc[j][3] * 0.125f);
        }
        __syncthreads();

        // ---- softmax: 4 threads per row, FMA-pipe exp ----
        {
            const int r = tid >> 2, sub = tid & 3;
            const float* row = &sf[SS_ + r * SSW + sub * 16];
            float vb[16];
            float mx = row[0];
#pragma unroll
            for (int i = 0; i < 16; i++) { vb[i] = row[i]; mx = fmaxf(mx, vb[i]); }
            mx = fmaxf(mx, __shfl_xor_sync(0xffffffffu, mx, 1));
            mx = fmaxf(mx, __shfl_xor_sync(0xffffffffu, mx, 2));
            const float mo = sf[RM_ + r];
            const float mn = fmaxf(mo, mx);
            float sum = 0.f;
            uint32_t hw8[8], lw8[8];
#pragma unroll
            for (int i = 0; i < 8; i++) {
                const float p0 = fexp(vb[2 * i] - mn);
                const float p1 = fexp(vb[2 * i + 1] - mn);
                sum += p0 + p1;
                split_pack(p0, p1, hw8[i], lw8[i]);
            }
            sum += __shfl_xor_sync(0xffffffffu, sum, 1);
            sum += __shfl_xor_sync(0xffffffffu, sum, 2);
            if (sub == 0) {
                const float fct = fexp(mo - mn);
                sf[RL_ + r] = sf[RL_ + r] * fct + sum;
                sf[RM_ + r] = mn;
                sf[RF_ + r] = fct;
            }
#pragma unroll
            for (int i = 0; i < 8; i++) {
                sw[PH_ + r * FW + sub * 8 + i] = hw8[i];
                sw[PL_ + r * FW + sub * 8 + i] = lw8[i];
            }
        }
        __syncthreads();

        // ---- O^T = V^T P^T : rescale then 3-pass accumulate ----
#pragma unroll
        for (int j = 0; j < 4; j++) {
            const float f0 = sf[RF_ + nw + 8 * j + 2 * tg];
            const float f1 = sf[RF_ + nw + 8 * j + 2 * tg + 1];
            oc[j][0] *= f0; oc[j][1] *= f1; oc[j][2] *= f0; oc[j][3] *= f1;
        }
#pragma unroll
        for (int ks = 0; ks < 4; ks++) {
            const int kw = 8 * ks + tg;
            uint32_t ah[4], al[4];
            ah[0] = sw[VH_ + (mw + g) * FW + kw];
            ah[1] = sw[VH_ + (mw + g + 8) * FW + kw];
            ah[2] = sw[VH_ + (mw + g) * FW + kw + 4];
            ah[3] = sw[VH_ + (mw + g + 8) * FW + kw + 4];
            al[0] = sw[VL_ + (mw + g) * FW + kw];
            al[1] = sw[VL_ + (mw + g + 8) * FW + kw];
            al[2] = sw[VL_ + (mw + g) * FW + kw + 4];
            al[3] = sw[VL_ + (mw + g + 8) * FW + kw + 4];
#pragma unroll
            for (int j = 0; j < 4; j++) {
                const int br = (nw + 8 * j + g) * FW + kw;
                uint32_t bh2[2] = { sw[PH_ + br], sw[PH_ + br + 4] };
                uint32_t bl2[2] = { sw[PL_ + br], sw[PL_ + br + 4] };
                mma_bf16(oc[j], ah, bh2);
                mma_bf16(oc[j], ah, bl2);
                mma_bf16(oc[j], al, bh2);
            }
        }
    }

    // ---- finalize: O^T[d][q] / l[q] -> g_attn[b, t=q0+q, h*64+d] ----
    const int bb = bh >> 4, hh = bh & 15;
#pragma unroll
    for (int j = 0; j < 4; j++) {
        const int qq = nw + 8 * j + 2 * tg;
        const float li0 = 1.f / sf[RL_ + qq];
        const float li1 = 1.f / sf[RL_ + qq + 1];
        const int d = mw + g;
        float* d0 = g_attn + ((size_t)(bb * T_ + q0 + qq)) * E_ + hh * 64 + d;
        float* d1 = g_attn + ((size_t)(bb * T_ + q0 + qq + 1)) * E_ + hh * 64 + d;
        d0[0] = oc[j][0] * li0;
        d1[0] = oc[j][1] * li1;
        d0[8] = oc[j][2] * li0;
        d1[8] = oc[j][3] * li1;
    }
}

// ---------------------------------------------------------------------------
extern "C" void kernel_launch(void* const* d_in, const int* in_sizes, int n_in,
                              void* d_out, int out_size)
{
    const float* query     = (const float*)d_in[0];
    const float* positions = (const float*)d_in[1];
    const float* in_w      = (const float*)d_in[2];
    const float* in_b      = (const float*)d_in[3];
    const float* out_w     = (const float*)d_in[4];
    const float* out_b     = (const float*)d_in[5];
    const float* freqs     = (const float*)d_in[6];
    float* out = (float*)d_out;

    cudaFuncSetAttribute(tc_gemm,
                         cudaFuncAttributeMaxDynamicSharedMemorySize,
                         GEMM_SMEM_WORDS * (int)sizeof(uint32_t));
    cudaFuncSetAttribute(flash_kernel,
                         cudaFuncAttributeMaxDynamicSharedMemorySize,
                         FAB_WORDS * (int)sizeof(uint32_t));

    // 1) QKV projection (split-BF16 mma.sync + ldmatrix), scattered head-major
    tc_gemm<<<dim3(N3_ / 128, M_ / 128), 512,
              GEMM_SMEM_WORDS * (int)sizeof(uint32_t)>>>(query, in_w, in_b,
                                                         nullptr, N3_, E_, 1);
    // 2) rotary on Q and K
    rotary_kernel<<<(B_ * H_ * T_ * F_) / 256, 256>>>(positions, freqs);
    // 3) attention (split-BF16 mma.sync + poly exp)
    flash_kernel<<<dim3(T_ / 64, B_ * H_), 256,
                   FAB_WORDS * (int)sizeof(uint32_t)>>>();
    // 4) output projection (split-BF16 mma.sync + ldmatrix)
    tc_gemm<<<dim3(E_ / 128, M_ / 128), 512,
              GEMM_SMEM_WORDS * (int)sizeof(uint32_t)>>>(nullptr, out_w, out_b,
                                                         out, E_, E_, 2);
}

// round 12
// speedup vs baseline: 2.5128x; 1.0684x over previous
#include <cuda_runtime.h>
#include <cuda_bf16.h>
#include <math.h>
#include <stdint.h>

#define B_  4
#define T_  2048
#define E_  1024
#define H_  16
#define D_  64
#define F_  32
#define M_  (B_*T_)     // 8192
#define N3_ (3*E_)      // 3072

// Scratch (device globals; no allocation allowed)
__device__ float g_q[B_*H_*T_*D_];
__device__ float g_k[B_*H_*T_*D_];
__device__ float g_v[B_*H_*T_*D_];
__device__ float g_attn[M_*E_];

// ---------------------------------------------------------------------------
// helpers
// ---------------------------------------------------------------------------
__device__ __forceinline__ uint32_t smem_u32(const void* p) {
    uint32_t a;
    asm("{ .reg .u64 t; cvta.to.shared.u64 t, %1; cvt.u32.u64 %0, t; }"
        : "=r"(a) : "l"(p));
    return a;
}
__device__ __forceinline__ void mma_bf16(float* d, const uint32_t* a, const uint32_t* b) {
    asm volatile(
        "mma.sync.aligned.m16n8k16.row.col.f32.bf16.bf16.f32 "
        "{%0,%1,%2,%3}, {%4,%5,%6,%7}, {%8,%9}, {%0,%1,%2,%3};"
        : "+f"(d[0]), "+f"(d[1]), "+f"(d[2]), "+f"(d[3])
        : "r"(a[0]), "r"(a[1]), "r"(a[2]), "r"(a[3]), "r"(b[0]), "r"(b[1]));
}
#define LDMX4(r, addr)                                                        \
    asm volatile("ldmatrix.sync.aligned.m8n8.x4.shared.b16 {%0,%1,%2,%3}, [%4];" \
        : "=r"((r)[0]), "=r"((r)[1]), "=r"((r)[2]), "=r"((r)[3]) : "r"(addr))
#define LDMX2(r, addr)                                                        \
    asm volatile("ldmatrix.sync.aligned.m8n8.x2.shared.b16 {%0,%1}, [%2];"    \
        : "=r"((r)[0]), "=r"((r)[1]) : "r"(addr))

// split x into hi+lo bf16, pack (x0,x1) -> words (x0 in low half)
__device__ __forceinline__ void split_pack(float x0, float x1, uint32_t& hi, uint32_t& lo) {
    __nv_bfloat162 h, l;
    h.x = __float2bfloat16(x0); h.y = __float2bfloat16(x1);
    l.x = __float2bfloat16(x0 - __bfloat162float(h.x));
    l.y = __float2bfloat16(x1 - __bfloat162float(h.y));
    hi = *(uint32_t*)&h; lo = *(uint32_t*)&l;
}
// fast exp on FMA/ALU pipes (no MUFU): rel err ~2e-6, valid for x <= 0
__device__ __forceinline__ float fexp(float x) {
    float t = fmaxf(x * 1.4426950408889634f, -126.0f);
    float tn = t + 12582912.0f;
    float nf = tn - 12582912.0f;
    float f  = t - nf;
    float p  = 0.0013333558f;
    p = fmaf(p, f, 0.0096181291f);
    p = fmaf(p, f, 0.0555041087f);
    p = fmaf(p, f, 0.2402265069f);
    p = fmaf(p, f, 0.6931471806f);
    p = fmaf(p, f, 1.0f);
    uint32_t eb = (__float_as_uint(tn) << 23) + 0x3F800000u;
    return p * __uint_as_float(eb);
}

// ===========================================================================
// Split-BF16 GEMM-NT, double-buffered + ldmatrix (validated R10, unchanged)
// ===========================================================================
#define SMSB  20
#define PLANE (128 * SMSB)        // 2560 words
#define BUFW  (4 * PLANE)         // 10240 words per buffer
#define GEMM_SMEM_WORDS (2 * BUFW)

__global__ __launch_bounds__(512)
void tc_gemm(const float* __restrict__ A_in, const float* __restrict__ W,
             const float* __restrict__ bias, float* __restrict__ C,
             int N, int K, int mode)
{
    extern __shared__ uint32_t smu[];
    const uint32_t sb = smem_u32(smu);

    const float* A = (mode == 2) ? g_attn : A_in;

    const int tid  = threadIdx.x;
    const int lane = tid & 31;
    const int warp = tid >> 5;
    const int row0 = blockIdx.y * 128;
    const int col0 = blockIdx.x * 128;

    const int wm = (warp >> 3) * 64;
    const int wn = (warp & 7) * 16;

    float acc[4][2][4];
#pragma unroll
    for (int mt = 0; mt < 4; mt++)
#pragma unroll
        for (int nt = 0; nt < 2; nt++)
#pragma unroll
            for (int i = 0; i < 4; i++) acc[mt][nt][i] = 0.f;

    const int lr0 = tid >> 3;
    const int lr1 = (tid + 512) >> 3;
    const int lc4 = (tid & 7) * 4;
    const int w0  = (tid & 7) * 2;
    const float* Ap0 = A + (size_t)(row0 + lr0) * K + lc4;
    const float* Ap1 = A + (size_t)(row0 + lr1) * K + lc4;
    const float* Wp0 = W + (size_t)(col0 + lr0) * K + lc4;
    const float* Wp1 = W + (size_t)(col0 + lr1) * K + lc4;

    const int q  = lane >> 3;
    const int rr = lane & 7;
    const uint32_t a_off = (uint32_t)(((q & 1) * 8 + rr) * SMSB + (q >> 1) * 4) * 4;
    const uint32_t b_off = (uint32_t)(rr * SMSB + (q & 1) * 4) * 4;

    const uint32_t ah_base = sb + (uint32_t)(wm * SMSB) * 4 + a_off;
    const uint32_t al_base = ah_base + PLANE * 4;
    const uint32_t bh_base = sb + (2 * PLANE + wn * SMSB) * 4 + b_off;
    const uint32_t bl_base = bh_base + PLANE * 4;

    float4 ra0 = *(const float4*)Ap0, ra1 = *(const float4*)Ap1;
    float4 rw0 = *(const float4*)Wp0, rw1 = *(const float4*)Wp1;

    auto store_chunk = [&](int buf) {
        uint32_t* Ah = smu + buf * BUFW;
        uint32_t* Al = Ah + PLANE;
        uint32_t* Bh = Al + PLANE;
        uint32_t* Bl = Bh + PLANE;
        uint32_t h0, l0, h1, l1;
        split_pack(ra0.x, ra0.y, h0, l0); split_pack(ra0.z, ra0.w, h1, l1);
        *(uint2*)&Ah[lr0 * SMSB + w0] = make_uint2(h0, h1);
        *(uint2*)&Al[lr0 * SMSB + w0] = make_uint2(l0, l1);
        split_pack(ra1.x, ra1.y, h0, l0); split_pack(ra1.z, ra1.w, h1, l1);
        *(uint2*)&Ah[lr1 * SMSB + w0] = make_uint2(h0, h1);
        *(uint2*)&Al[lr1 * SMSB + w0] = make_uint2(l0, l1);
        split_pack(rw0.x, rw0.y, h0, l0); split_pack(rw0.z, rw0.w, h1, l1);
        *(uint2*)&Bh[lr0 * SMSB + w0] = make_uint2(h0, h1);
        *(uint2*)&Bl[lr0 * SMSB + w0] = make_uint2(l0, l1);
        split_pack(rw1.x, rw1.y, h0, l0); split_pack(rw1.z, rw1.w, h1, l1);
        *(uint2*)&Bh[lr1 * SMSB + w0] = make_uint2(h0, h1);
        *(uint2*)&Bl[lr1 * SMSB + w0] = make_uint2(l0, l1);
    };

    store_chunk(0);
    __syncthreads();

    const int nch = K / 32;
    for (int c = 0; c < nch; c++) {
        if (c + 1 < nch) {
            const int ko = (c + 1) * 32;
            ra0 = *(const float4*)(Ap0 + ko); ra1 = *(const float4*)(Ap1 + ko);
            rw0 = *(const float4*)(Wp0 + ko); rw1 = *(const float4*)(Wp1 + ko);
        }

        const uint32_t bofs = (uint32_t)((c & 1) * BUFW) * 4;
#pragma unroll
        for (int ks = 0; ks < 2; ks++) {
            const uint32_t kb = bofs + ks * 32;
            uint32_t bhf[2][2], blf[2][2];
#pragma unroll
            for (int nt = 0; nt < 2; nt++) {
                LDMX2(bhf[nt], bh_base + nt * 640 + kb);
                LDMX2(blf[nt], bl_base + nt * 640 + kb);
            }
#pragma unroll
            for (int mt = 0; mt < 4; mt++) {
                uint32_t ah[4], al[4];
                LDMX4(ah, ah_base + mt * 1280 + kb);
                LDMX4(al, al_base + mt * 1280 + kb);
#pragma unroll
                for (int nt = 0; nt < 2; nt++) {
                    mma_bf16(acc[mt][nt], ah, bhf[nt]);
                    mma_bf16(acc[mt][nt], ah, blf[nt]);
                    mma_bf16(acc[mt][nt], al, bhf[nt]);
                }
            }
        }

        if (c + 1 < nch) store_chunk((c + 1) & 1);
        __syncthreads();
    }

    const int g  = lane >> 2;
    const int tg = lane & 3;
#pragma unroll
    for (int mt = 0; mt < 4; mt++) {
#pragma unroll
        for (int nt = 0; nt < 2; nt++) {
#pragma unroll
            for (int half = 0; half < 2; half++) {
                const int m = row0 + wm + mt * 16 + g + half * 8;
                const int n = col0 + wn + nt * 8 + 2 * tg;
                const float vx = acc[mt][nt][2 * half]     + bias[n];
                const float vy = acc[mt][nt][2 * half + 1] + bias[n + 1];
                if (mode == 1) {
                    const int bb = m >> 11, t = m & 2047;
                    const int sec = n >> 10;
                    const int nn = n & 1023;
                    const int h = nn >> 6, d = nn & 63;
                    float* dst = ((sec == 0) ? g_q : (sec == 1) ? g_k : g_v)
                                 + ((size_t)(bb * H_ + h) * T_ + t) * D_ + d;
                    dst[0] = vx; dst[1] = vy;
                } else {
                    float* dst = C + (size_t)m * N + n;
                    dst[0] = vx; dst[1] = vy;
                }
            }
        }
    }
}

// ---------------------------------------------------------------------------
// Rotary (unchanged)
// ---------------------------------------------------------------------------
__global__ __launch_bounds__(256)
void rotary_kernel(const float* __restrict__ pos, const float* __restrict__ freqs)
{
    const int idx = blockIdx.x * blockDim.x + threadIdx.x;
    const int f = idx & 31;
    const int t = (idx >> 5) & 2047;
    const int h = (idx >> 16) & 15;
    const int b = idx >> 20;

    const float* p  = pos   + ((size_t)b * T_ + t) * 3;
    const float* fr = freqs + ((size_t)h * F_ + f) * 3;
    const float ang = p[0] * fr[0] + p[1] * fr[1] + p[2] * fr[2];
    float s, c;
    sincosf(ang, &s, &c);

    const size_t base = ((size_t)(b * H_ + h) * T_ + t) * D_ + 2 * f;
    const float q0 = g_q[base], q1 = g_q[base + 1];
    g_q[base]     = q0 * c - q1 * s;
    g_q[base + 1] = q0 * s + q1 * c;
    const float k0 = g_k[base], k1 = g_k[base + 1];
    g_k[base]     = k0 * c - k1 * s;
    g_k[base + 1] = k0 * s + k1 * c;
}

// ===========================================================================
// Flash attention v2: 128-query tiles, 512 threads (16 warps), ldmatrix
// fragment loads, register prefetch of next K/V tile.
// S = Q K^T (128x64), O^T = V^T P^T (64x128); 3-pass split bf16.
// ===========================================================================
#define FW   36
#define QH_  0
#define QL_  (128*FW)            // 4608
#define KH_  (2*128*FW)          // 9216
#define KL_  (KH_ + 64*FW)       // 11520
#define VH_  (KL_ + 64*FW)       // 13824
#define VL_  (VH_ + 64*FW)       // 16128
#define PH_  (VL_ + 64*FW)       // 18432
#define PL_  (PH_ + 128*FW)      // 23040
#define SS_  (PL_ + 128*FW)      // 27648
#define SSW  66
#define RM_  (SS_ + 128*SSW)     // 36096
#define RL_  (RM_ + 128)
#define RF_  (RL_ + 128)
#define FAB_WORDS (RF_ + 128)    // 36480 words = 145920 B

__global__ __launch_bounds__(512)
void flash_kernel()
{
    extern __shared__ uint32_t sw[];
    float* sf = (float*)sw;
    const uint32_t sb = smem_u32(sw);

    const int tid  = threadIdx.x;
    const int lane = tid & 31;
    const int warp = tid >> 5;
    const int bh   = blockIdx.y;
    const int q0   = blockIdx.x * 128;

    const float*  Qg  = g_q + ((size_t)bh * T_ + q0) * D_;
    const float2* Kg2 = (const float2*)(g_k + (size_t)bh * T_ * D_);
    const float*  Vg  = g_v + (size_t)bh * T_ * D_;

    const int g  = lane >> 2;          // 0..7
    const int tg = lane & 3;           // 0..3
    const int qq4 = lane >> 3;         // 0..3 (ldmatrix address group)
    const int rr  = lane & 7;

    // ldmatrix lane byte-offsets (FW rows are 144B = 9*16B -> 16B aligned)
    const uint32_t a_off = (uint32_t)((((qq4 & 1) * 8 + rr) * FW + (qq4 >> 1) * 4)) * 4;
    const uint32_t b_off = (uint32_t)(rr * FW + (qq4 & 1) * 4) * 4;

    // S phase warp tiles: 128x64 -> 4x4 warps, 32x16 each
    const int wmS = (warp >> 2) * 32;
    const int wnS = (warp & 3) * 16;
    // O phase warp tiles: 64x128 -> 4x4 warps, 16x32 each
    const int wmO = (warp >> 2) * 16;
    const int wnO = (warp & 3) * 32;

    // ---- load Q planes (once): 128 rows x 32 wordpairs ----
#pragma unroll
    for (int it = 0; it < 8; it++) {
        const int idx = tid + it * 512;
        const int r = idx >> 5, dp = idx & 31;
        const float2 v = ((const float2*)Qg)[r * 32 + dp];
        uint32_t hi, lo;
        split_pack(v.x, v.y, hi, lo);
        sw[QH_ + r * FW + dp] = hi;
        sw[QL_ + r * FW + dp] = lo;
    }
    if (tid < 128) { sf[RM_ + tid] = -INFINITY; sf[RL_ + tid] = 0.f; }

    float oc[4][4];
#pragma unroll
    for (int nt = 0; nt < 4; nt++)
#pragma unroll
        for (int i = 0; i < 4; i++) oc[nt][i] = 0.f;

    // ---- prefetch first K/V tile into registers ----
    const int kp = tid >> 4;           // 0..31 (V keypair)
    const int dv = tid & 15;           // V d base
    float2 kr[4];
    float vr0[4], vr1[4];
#pragma unroll
    for (int it = 0; it < 4; it++) {
        const int idx = tid + it * 512;
        kr[it] = Kg2[(size_t)(idx >> 5) * 32 + (idx & 31)];
        const int d = dv + 16 * it;
        vr0[it] = Vg[(size_t)(2 * kp) * 64 + d];
        vr1[it] = Vg[(size_t)(2 * kp + 1) * 64 + d];
    }

    for (int j0 = 0; j0 < T_; j0 += 64) {
        __syncthreads();               // prev-iter consumers done

        // ---- store K planes from regs ----
#pragma unroll
        for (int it = 0; it < 4; it++) {
            const int idx = tid + it * 512;
            const int r = idx >> 5, dp = idx & 31;
            uint32_t hi, lo;
            split_pack(kr[it].x, kr[it].y, hi, lo);
            sw[KH_ + r * FW + dp] = hi;
            sw[KL_ + r * FW + dp] = lo;
        }
        // ---- store V transposed planes from regs: Vt[d][keypair] ----
#pragma unroll
        for (int it = 0; it < 4; it++) {
            const int d = dv + 16 * it;
            uint32_t hi, lo;
            split_pack(vr0[it], vr1[it], hi, lo);
            sw[VH_ + d * FW + kp] = hi;
            sw[VL_ + d * FW + kp] = lo;
        }
        __syncthreads();

        // ---- prefetch next K/V tile (overlaps S/softmax/O phases) ----
        if (j0 + 64 < T_) {
            const int jn = j0 + 64;
#pragma unroll
            for (int it = 0; it < 4; it++) {
                const int idx = tid + it * 512;
                kr[it] = Kg2[(size_t)(jn + (idx >> 5)) * 32 + (idx & 31)];
                const int d = dv + 16 * it;
                vr0[it] = Vg[(size_t)(jn + 2 * kp) * 64 + d];
                vr1[it] = Vg[(size_t)(jn + 2 * kp + 1) * 64 + d];
            }
        }

        // ---- S = Q K^T (3-pass split bf16, ldmatrix) ----
        float sc[2][2][4];
#pragma unroll
        for (int mt = 0; mt < 2; mt++)
#pragma unroll
            for (int nt = 0; nt < 2; nt++)
#pragma unroll
                for (int i = 0; i < 4; i++) sc[mt][nt][i] = 0.f;

#pragma unroll
        for (int ks = 0; ks < 4; ks++) {
            const uint32_t kb = ks * 32;
            uint32_t bhf[2][2], blf[2][2];
#pragma unroll
            for (int nt = 0; nt < 2; nt++) {
                const uint32_t bb2 = (uint32_t)((wnS + nt * 8) * FW) * 4 + b_off + kb;
                LDMX2(bhf[nt], sb + KH_ * 4 + bb2);
                LDMX2(blf[nt], sb + KL_ * 4 + bb2);
            }
#pragma unroll
            for (int mt = 0; mt < 2; mt++) {
                const uint32_t ab = (uint32_t)((wmS + mt * 16) * FW) * 4 + a_off + kb;
                uint32_t ah[4], al[4];
                LDMX4(ah, sb + QH_ * 4 + ab);
                LDMX4(al, sb + QL_ * 4 + ab);
#pragma unroll
                for (int nt = 0; nt < 2; nt++) {
                    mma_bf16(sc[mt][nt], ah, bhf[nt]);
                    mma_bf16(sc[mt][nt], ah, blf[nt]);
                    mma_bf16(sc[mt][nt], al, bhf[nt]);
                }
            }
        }
#pragma unroll
        for (int mt = 0; mt < 2; mt++)
#pragma unroll
            for (int nt = 0; nt < 2; nt++) {
                const int row = wmS + mt * 16 + g;
                const int col = wnS + nt * 8 + 2 * tg;
                *(float2*)&sf[SS_ + row * SSW + col] =
                    make_float2(sc[mt][nt][0] * 0.125f, sc[mt][nt][1] * 0.125f);
                *(float2*)&sf[SS_ + (row + 8) * SSW + col] =
                    make_float2(sc[mt][nt][2] * 0.125f, sc[mt][nt][3] * 0.125f);
            }
        __syncthreads();

        // ---- softmax: 4 threads per row (128 rows), FMA-pipe exp ----
        {
            const int r = tid >> 2, sub = tid & 3;
            const float* row = &sf[SS_ + r * SSW + sub * 16];
            float vb[16];
            float mx = row[0];
#pragma unroll
            for (int i = 0; i < 16; i++) { vb[i] = row[i]; mx = fmaxf(mx, vb[i]); }
            mx = fmaxf(mx, __shfl_xor_sync(0xffffffffu, mx, 1));
            mx = fmaxf(mx, __shfl_xor_sync(0xffffffffu, mx, 2));
            const float mo = sf[RM_ + r];
            const float mn = fmaxf(mo, mx);
            float sum = 0.f;
            uint32_t hw8[8], lw8[8];
#pragma unroll
            for (int i = 0; i < 8; i++) {
                const float p0 = fexp(vb[2 * i] - mn);
                const float p1 = fexp(vb[2 * i + 1] - mn);
                sum += p0 + p1;
                split_pack(p0, p1, hw8[i], lw8[i]);
            }
            sum += __shfl_xor_sync(0xffffffffu, sum, 1);
            sum += __shfl_xor_sync(0xffffffffu, sum, 2);
            if (sub == 0) {
                const float fct = fexp(mo - mn);
                sf[RL_ + r] = sf[RL_ + r] * fct + sum;
                sf[RM_ + r] = mn;
                sf[RF_ + r] = fct;
            }
#pragma unroll
            for (int i = 0; i < 8; i++) {
                sw[PH_ + r * FW + sub * 8 + i] = hw8[i];
                sw[PL_ + r * FW + sub * 8 + i] = lw8[i];
            }
        }
        __syncthreads();

        // ---- O^T = V^T P^T : rescale then 3-pass accumulate (ldmatrix) ----
#pragma unroll
        for (int nt = 0; nt < 4; nt++) {
            const float f0 = sf[RF_ + wnO + 8 * nt + 2 * tg];
            const float f1 = sf[RF_ + wnO + 8 * nt + 2 * tg + 1];
            oc[nt][0] *= f0; oc[nt][1] *= f1; oc[nt][2] *= f0; oc[nt][3] *= f1;
        }
#pragma unroll
        for (int ks = 0; ks < 4; ks++) {
            const uint32_t kb = ks * 32;
            const uint32_t ab = (uint32_t)(wmO * FW) * 4 + a_off + kb;
            uint32_t ah[4], al[4];
            LDMX4(ah, sb + VH_ * 4 + ab);
            LDMX4(al, sb + VL_ * 4 + ab);
#pragma unroll
            for (int nt = 0; nt < 4; nt++) {
                const uint32_t bb2 = (uint32_t)((wnO + nt * 8) * FW) * 4 + b_off + kb;
                uint32_t bhf[2], blf[2];
                LDMX2(bhf, sb + PH_ * 4 + bb2);
                LDMX2(blf, sb + PL_ * 4 + bb2);
                mma_bf16(oc[nt], ah, bhf);
                mma_bf16(oc[nt], ah, blf);
                mma_bf16(oc[nt], al, bhf);
            }
        }
    }

    // ---- finalize: O^T[d][q] / l[q] -> g_attn[b, t=q0+q, h*64+d] ----
    const int bb = bh >> 4, hh = bh & 15;
#pragma unroll
    for (int nt = 0; nt < 4; nt++) {
        const int qq = wnO + 8 * nt + 2 * tg;
        const float li0 = 1.f / sf[RL_ + qq];
        const float li1 = 1.f / sf[RL_ + qq + 1];
        const int d = wmO + g;
        float* d0 = g_attn + ((size_t)(bb * T_ + q0 + qq)) * E_ + hh * 64 + d;
        float* d1 = g_attn + ((size_t)(bb * T_ + q0 + qq + 1)) * E_ + hh * 64 + d;
        d0[0] = oc[nt][0] * li0;
        d1[0] = oc[nt][1] * li1;
        d0[8] = oc[nt][2] * li0;
        d1[8] = oc[nt][3] * li1;
    }
}

// ---------------------------------------------------------------------------
extern "C" void kernel_launch(void* const* d_in, const int* in_sizes, int n_in,
                              void* d_out, int out_size)
{
    const float* query     = (const float*)d_in[0];
    const float* positions = (const float*)d_in[1];
    const float* in_w      = (const float*)d_in[2];
    const float* in_b      = (const float*)d_in[3];
    const float* out_w     = (const float*)d_in[4];
    const float* out_b     = (const float*)d_in[5];
    const float* freqs     = (const float*)d_in[6];
    float* out = (float*)d_out;

    cudaFuncSetAttribute(tc_gemm,
                         cudaFuncAttributeMaxDynamicSharedMemorySize,
                         GEMM_SMEM_WORDS * (int)sizeof(uint32_t));
    cudaFuncSetAttribute(flash_kernel,
                         cudaFuncAttributeMaxDynamicSharedMemorySize,
                         FAB_WORDS * (int)sizeof(uint32_t));

    // 1) QKV projection (split-BF16 mma.sync + ldmatrix), scattered head-major
    tc_gemm<<<dim3(N3_ / 128, M_ / 128), 512,
              GEMM_SMEM_WORDS * (int)sizeof(uint32_t)>>>(query, in_w, in_b,
                                                         nullptr, N3_, E_, 1);
    // 2) rotary on Q and K
    rotary_kernel<<<(B_ * H_ * T_ * F_) / 256, 256>>>(positions, freqs);
    // 3) attention (128-q tiles, ldmatrix, prefetch)
    flash_kernel<<<dim3(T_ / 128, B_ * H_), 512,
                   FAB_WORDS * (int)sizeof(uint32_t)>>>();
    // 4) output projection (split-BF16 mma.sync + ldmatrix)
    tc_gemm<<<dim3(E_ / 128, M_ / 128), 512,
              GEMM_SMEM_WORDS * (int)sizeof(uint32_t)>>>(nullptr, out_w, out_b,
                                                         out, E_, E_, 2);
}

// round 16
// speedup vs baseline: 2.5381x; 1.0101x over previous
// R15: R13-fixed + __align__(16) on all device scratch arrays.
// cp.async.cg requires 16B-aligned global sources; bf16 __device__ arrays
// default to .align 2 in PTX — a misaligned placement faults every launch,
// matching the repeated container failures. Alignment is now explicit.
#include <cuda_runtime.h>
#include <cuda_bf16.h>
#include <math.h>
#include <stdint.h>

#define B_  4
#define T_  2048
#define E_  1024
#define H_  16
#define D_  64
#define F_  32
#define M_  (B_*T_)     // 8192
#define N3_ (3*E_)      // 3072

// Scratch (device globals; no allocation allowed). 16B-aligned explicitly.
__device__ __align__(16) float g_q[B_*H_*T_*D_];
__device__ __align__(16) float g_k[B_*H_*T_*D_];
__device__ __align__(16) float g_v[B_*H_*T_*D_];
// bf16 hi/lo planes
__device__ __align__(16) __nv_bfloat16 g_qh[M_*E_],  g_ql[M_*E_];    // query
__device__ __align__(16) __nv_bfloat16 g_iwh[N3_*E_], g_iwl[N3_*E_]; // in_w
__device__ __align__(16) __nv_bfloat16 g_owh[E_*E_],  g_owl[E_*E_];  // out_w
__device__ __align__(16) __nv_bfloat16 g_ah[M_*E_],  g_al[M_*E_];    // attn out

// ---------------------------------------------------------------------------
// helpers
// ---------------------------------------------------------------------------
__device__ __forceinline__ uint32_t smem_u32(const void* p) {
    uint32_t a;
    asm("{ .reg .u64 t; cvta.to.shared.u64 t, %1; cvt.u32.u64 %0, t; }"
        : "=r"(a) : "l"(p));
    return a;
}
__device__ __forceinline__ void mma_bf16(float* d, const uint32_t* a, const uint32_t* b) {
    asm volatile(
        "mma.sync.aligned.m16n8k16.row.col.f32.bf16.bf16.f32 "
        "{%0,%1,%2,%3}, {%4,%5,%6,%7}, {%8,%9}, {%0,%1,%2,%3};"
        : "+f"(d[0]), "+f"(d[1]), "+f"(d[2]), "+f"(d[3])
        : "r"(a[0]), "r"(a[1]), "r"(a[2]), "r"(a[3]), "r"(b[0]), "r"(b[1]));
}
#define LDMX4(r, addr)                                                        \
    asm volatile("ldmatrix.sync.aligned.m8n8.x4.shared.b16 {%0,%1,%2,%3}, [%4];" \
        : "=r"((r)[0]), "=r"((r)[1]), "=r"((r)[2]), "=r"((r)[3]) : "r"(addr))
#define LDMX2(r, addr)                                                        \
    asm volatile("ldmatrix.sync.aligned.m8n8.x2.shared.b16 {%0,%1}, [%2];"    \
        : "=r"((r)[0]), "=r"((r)[1]) : "r"(addr))
#define CP_ASYNC16(dst, src) \
    asm volatile("cp.async.cg.shared.global [%0], [%1], 16;" :: "r"(dst), "l"(src))
#define CP_COMMIT() asm volatile("cp.async.commit_group;" ::: "memory")
#define CP_WAIT1()  asm volatile("cp.async.wait_group 1;" ::: "memory")
#define CP_WAIT0()  asm volatile("cp.async.wait_group 0;" ::: "memory")

// split x into hi+lo bf16, pack (x0,x1) -> words (x0 in low half)
__device__ __forceinline__ void split_pack(float x0, float x1, uint32_t& hi, uint32_t& lo) {
    __nv_bfloat162 h, l;
    h.x = __float2bfloat16(x0); h.y = __float2bfloat16(x1);
    l.x = __float2bfloat16(x0 - __bfloat162float(h.x));
    l.y = __float2bfloat16(x1 - __bfloat162float(h.y));
    hi = *(uint32_t*)&h; lo = *(uint32_t*)&l;
}
// fast exp on FMA/ALU pipes (no MUFU): rel err ~2e-6, valid for x <= 0
__device__ __forceinline__ float fexp(float x) {
    float t = fmaxf(x * 1.4426950408889634f, -126.0f);
    float tn = t + 12582912.0f;
    float nf = tn - 12582912.0f;
    float f  = t - nf;
    float p  = 0.0013333558f;
    p = fmaf(p, f, 0.0096181291f);
    p = fmaf(p, f, 0.0555041087f);
    p = fmaf(p, f, 0.2402265069f);
    p = fmaf(p, f, 0.6931471806f);
    p = fmaf(p, f, 1.0f);
    uint32_t eb = (__float_as_uint(tn) << 23) + 0x3F800000u;
    return p * __uint_as_float(eb);
}

// ---------------------------------------------------------------------------
// fp32 -> hi/lo bf16 plane conversion. which: 0=query, 1=in_w, 2=out_w
// ---------------------------------------------------------------------------
__global__ __launch_bounds__(256)
void convert_kernel(const float* __restrict__ src, int n2, int which)
{
    const int idx = blockIdx.x * blockDim.x + threadIdx.x;
    if (idx >= n2) return;
    uint32_t *dh, *dl;
    if (which == 0)      { dh = (uint32_t*)g_qh;  dl = (uint32_t*)g_ql;  }
    else if (which == 1) { dh = (uint32_t*)g_iwh; dl = (uint32_t*)g_iwl; }
    else                 { dh = (uint32_t*)g_owh; dl = (uint32_t*)g_owl; }
    const float2 v = ((const float2*)src)[idx];
    uint32_t h, l;
    split_pack(v.x, v.y, h, l);
    dh[idx] = h; dl[idx] = l;
}

// ===========================================================================
// Split-BF16 GEMM-NT from pre-converted planes, cp.async double-buffer.
// C[m,n] = sum_k A[m,k]*W[n,k] + bias[n], 3-pass hi/lo, m16n8k16 + ldmatrix.
// 128x128 C tile, BK=32, 512 threads, 2 CTAs/SM target.
//   mode 1: A = query planes, W = in_w planes, scatter into g_q/g_k/g_v
//   mode 2: A = attn planes (from flash), W = out_w planes, C = output
// ===========================================================================
#define SMSB  20
#define PLANE (128 * SMSB)        // 2560 words
#define BUFW  (4 * PLANE)         // 10240 words per buffer
#define GEMM_SMEM_WORDS (2 * BUFW)  // 81920 bytes

__global__ __launch_bounds__(512, 2)
void tc_gemm(const float* __restrict__ bias, float* __restrict__ C,
             int N, int K, int mode)
{
    extern __shared__ uint32_t smu[];
    const uint32_t sb = smem_u32(smu);

    const __nv_bfloat16 *Ahg, *Alg, *Bhg, *Blg;
    if (mode == 1) { Ahg = g_qh; Alg = g_ql; Bhg = g_iwh; Blg = g_iwl; }
    else           { Ahg = g_ah; Alg = g_al; Bhg = g_owh; Blg = g_owl; }

    const int tid  = threadIdx.x;
    const int lane = tid & 31;
    const int warp = tid >> 5;
    const int row0 = blockIdx.y * 128;
    const int col0 = blockIdx.x * 128;

    const int wm = (warp >> 3) * 64;
    const int wn = (warp & 7) * 16;

    float acc[4][2][4];
#pragma unroll
    for (int mt = 0; mt < 4; mt++)
#pragma unroll
        for (int nt = 0; nt < 2; nt++)
#pragma unroll
            for (int i = 0; i < 4; i++) acc[mt][nt][i] = 0.f;

    // ---- cp.async mapping: thread -> (row, 16B segment); plane p in 0..3
    const int crow = tid >> 2;         // 0..127
    const int cseg = tid & 3;          // 0..3
    const __nv_bfloat16* srcs[4];
    srcs[0] = Ahg + (size_t)(row0 + crow) * K + cseg * 8;
    srcs[1] = Alg + (size_t)(row0 + crow) * K + cseg * 8;
    srcs[2] = Bhg + (size_t)(col0 + crow) * K + cseg * 8;
    srcs[3] = Blg + (size_t)(col0 + crow) * K + cseg * 8;
    const uint32_t dstw = (uint32_t)(crow * SMSB + cseg * 4);  // word off in plane

    // ---- ldmatrix per-lane addresses ----
    const int q  = lane >> 3;
    const int rr = lane & 7;
    const uint32_t a_off = (uint32_t)(((q & 1) * 8 + rr) * SMSB + (q >> 1) * 4) * 4;
    const uint32_t b_off = (uint32_t)(rr * SMSB + (q & 1) * 4) * 4;
    const uint32_t ah_base = sb + (uint32_t)(wm * SMSB) * 4 + a_off;
    const uint32_t al_base = ah_base + PLANE * 4;
    const uint32_t bh_base = sb + (2 * PLANE + wn * SMSB) * 4 + b_off;
    const uint32_t bl_base = bh_base + PLANE * 4;

    const int nch = K / 32;

    // issue chunk c into buffer buf
    auto issue = [&](int c, int buf) {
        const int ko = c * 32;
#pragma unroll
        for (int p = 0; p < 4; p++)
            CP_ASYNC16(sb + (uint32_t)(buf * BUFW + p * PLANE + dstw) * 4,
                       (const void*)(srcs[p] + ko));
        CP_COMMIT();
    };

    issue(0, 0);
    issue(1, 1);

    for (int c = 0; c < nch; c++) {
        if (c + 1 < nch) CP_WAIT1(); else CP_WAIT0();
        __syncthreads();

        const uint32_t bofs = (uint32_t)((c & 1) * BUFW) * 4;
#pragma unroll
        for (int ks = 0; ks < 2; ks++) {
            const uint32_t kb = bofs + ks * 32;
            uint32_t bhf[2][2], blf[2][2];
#pragma unroll
            for (int nt = 0; nt < 2; nt++) {
                // n-tiles are 8 rows apart: stride 8*SMSB*4 = 640 bytes
                LDMX2(bhf[nt], bh_base + nt * (8 * SMSB * 4) + kb);
                LDMX2(blf[nt], bl_base + nt * (8 * SMSB * 4) + kb);
            }
#pragma unroll
            for (int mt = 0; mt < 4; mt++) {
                // m-tiles are 16 rows apart: stride 16*SMSB*4 = 1280 bytes
                uint32_t ah[4], al[4];
                LDMX4(ah, ah_base + mt * (16 * SMSB * 4) + kb);
                LDMX4(al, al_base + mt * (16 * SMSB * 4) + kb);
#pragma unroll
                for (int nt = 0; nt < 2; nt++) {
                    mma_bf16(acc[mt][nt], ah, bhf[nt]);
                    mma_bf16(acc[mt][nt], ah, blf[nt]);
                    mma_bf16(acc[mt][nt], al, bhf[nt]);
                }
            }
        }
        __syncthreads();
        if (c + 2 < nch) issue(c + 2, c & 1);
    }

    // -------- epilogue --------
    const int g  = lane >> 2;
    const int tg = lane & 3;
#pragma unroll
    for (int mt = 0; mt < 4; mt++) {
#pragma unroll
        for (int nt = 0; nt < 2; nt++) {
#pragma unroll
            for (int half = 0; half < 2; half++) {
                const int m = row0 + wm + mt * 16 + g + half * 8;
                const int n = col0 + wn + nt * 8 + 2 * tg;
                const float vx = acc[mt][nt][2 * half]     + bias[n];
                const float vy = acc[mt][nt][2 * half + 1] + bias[n + 1];
                if (mode == 1) {
                    const int bb = m >> 11, t = m & 2047;
                    const int sec = n >> 10;
                    const int nn = n & 1023;
                    const int h = nn >> 6, d = nn & 63;
                    float* dst = ((sec == 0) ? g_q : (sec == 1) ? g_k : g_v)
                                 + ((size_t)(bb * H_ + h) * T_ + t) * D_ + d;
                    dst[0] = vx; dst[1] = vy;
                } else {
                    float* dst = C + (size_t)m * N + n;
                    dst[0] = vx; dst[1] = vy;
                }
            }
        }
    }
}

// ---------------------------------------------------------------------------
// Rotary (unchanged)
// ---------------------------------------------------------------------------
__global__ __launch_bounds__(256)
void rotary_kernel(const float* __restrict__ pos, const float* __restrict__ freqs)
{
    const int idx = blockIdx.x * blockDim.x + threadIdx.x;
    const int f = idx & 31;
    const int t = (idx >> 5) & 2047;
    const int h = (idx >> 16) & 15;
    const int b = idx >> 20;

    const float* p  = pos   + ((size_t)b * T_ + t) * 3;
    const float* fr = freqs + ((size_t)h * F_ + f) * 3;
    const float ang = p[0] * fr[0] + p[1] * fr[1] + p[2] * fr[2];
    float s, c;
    sincosf(ang, &s, &c);

    const size_t base = ((size_t)(b * H_ + h) * T_ + t) * D_ + 2 * f;
    const float q0 = g_q[base], q1 = g_q[base + 1];
    g_q[base]     = q0 * c - q1 * s;
    g_q[base + 1] = q0 * s + q1 * c;
    const float k0 = g_k[base], k1 = g_k[base + 1];
    g_k[base]     = k0 * c - k1 * s;
    g_k[base + 1] = k0 * s + k1 * c;
}

// ===========================================================================
// Flash attention (R11 structure); epilogue emits g_ah/g_al bf16 planes.
// ===========================================================================
#define FW   36
#define QH_  0
#define QL_  (128*FW)
#define KH_  (2*128*FW)
#define KL_  (KH_ + 64*FW)
#define VH_  (KL_ + 64*FW)
#define VL_  (VH_ + 64*FW)
#define PH_  (VL_ + 64*FW)
#define PL_  (PH_ + 128*FW)
#define SS_  (PL_ + 128*FW)
#define SSW  66
#define RM_  (SS_ + 128*SSW)
#define RL_  (RM_ + 128)
#define RF_  (RL_ + 128)
#define FAB_WORDS (RF_ + 128)

__device__ __forceinline__ void store_hl(size_t idx, float v) {
    const __nv_bfloat16 h = __float2bfloat16(v);
    g_ah[idx] = h;
    g_al[idx] = __float2bfloat16(v - __bfloat162float(h));
}

__global__ __launch_bounds__(512)
void flash_kernel()
{
    extern __shared__ uint32_t sw[];
    float* sf = (float*)sw;
    const uint32_t sb = smem_u32(sw);

    const int tid  = threadIdx.x;
    const int lane = tid & 31;
    const int warp = tid >> 5;
    const int bh   = blockIdx.y;
    const int q0   = blockIdx.x * 128;

    const float*  Qg  = g_q + ((size_t)bh * T_ + q0) * D_;
    const float2* Kg2 = (const float2*)(g_k + (size_t)bh * T_ * D_);
    const float*  Vg  = g_v + (size_t)bh * T_ * D_;

    const int g  = lane >> 2;
    const int tg = lane & 3;
    const int qq4 = lane >> 3;
    const int rr  = lane & 7;

    const uint32_t a_off = (uint32_t)((((qq4 & 1) * 8 + rr) * FW + (qq4 >> 1) * 4)) * 4;
    const uint32_t b_off = (uint32_t)(rr * FW + (qq4 & 1) * 4) * 4;

    const int wmS = (warp >> 2) * 32;
    const int wnS = (warp & 3) * 16;
    const int wmO = (warp >> 2) * 16;
    const int wnO = (warp & 3) * 32;

#pragma unroll
    for (int it = 0; it < 8; it++) {
        const int idx = tid + it * 512;
        const int r = idx >> 5, dp = idx & 31;
        const float2 v = ((const float2*)Qg)[r * 32 + dp];
        uint32_t hi, lo;
        split_pack(v.x, v.y, hi, lo);
        sw[QH_ + r * FW + dp] = hi;
        sw[QL_ + r * FW + dp] = lo;
    }
    if (tid < 128) { sf[RM_ + tid] = -INFINITY; sf[RL_ + tid] = 0.f; }

    float oc[4][4];
#pragma unroll
    for (int nt = 0; nt < 4; nt++)
#pragma unroll
        for (int i = 0; i < 4; i++) oc[nt][i] = 0.f;

    const int kp = tid >> 4;
    const int dv = tid & 15;
    float2 kr[4];
    float vr0[4], vr1[4];
#pragma unroll
    for (int it = 0; it < 4; it++) {
        const int idx = tid + it * 512;
        kr[it] = Kg2[(size_t)(idx >> 5) * 32 + (idx & 31)];
        const int d = dv + 16 * it;
        vr0[it] = Vg[(size_t)(2 * kp) * 64 + d];
        vr1[it] = Vg[(size_t)(2 * kp + 1) * 64 + d];
    }

    for (int j0 = 0; j0 < T_; j0 += 64) {
        __syncthreads();

#pragma unroll
        for (int it = 0; it < 4; it++) {
            const int idx = tid + it * 512;
            const int r = idx >> 5, dp = idx & 31;
            uint32_t hi, lo;
            split_pack(kr[it].x, kr[it].y, hi, lo);
            sw[KH_ + r * FW + dp] = hi;
            sw[KL_ + r * FW + dp] = lo;
        }
#pragma unroll
        for (int it = 0; it < 4; it++) {
            const int d = dv + 16 * it;
            uint32_t hi, lo;
            split_pack(vr0[it], vr1[it], hi, lo);
            sw[VH_ + d * FW + kp] = hi;
            sw[VL_ + d * FW + kp] = lo;
        }
        __syncthreads();

        if (j0 + 64 < T_) {
            const int jn = j0 + 64;
#pragma unroll
            for (int it = 0; it < 4; it++) {
                const int idx = tid + it * 512;
                kr[it] = Kg2[(size_t)(jn + (idx >> 5)) * 32 + (idx & 31)];
                const int d = dv + 16 * it;
                vr0[it] = Vg[(size_t)(jn + 2 * kp) * 64 + d];
                vr1[it] = Vg[(size_t)(jn + 2 * kp + 1) * 64 + d];
            }
        }

        float sc[2][2][4];
#pragma unroll
        for (int mt = 0; mt < 2; mt++)
#pragma unroll
            for (int nt = 0; nt < 2; nt++)
#pragma unroll
                for (int i = 0; i < 4; i++) sc[mt][nt][i] = 0.f;

#pragma unroll
        for (int ks = 0; ks < 4; ks++) {
            const uint32_t kb = ks * 32;
            uint32_t bhf[2][2], blf[2][2];
#pragma unroll
            for (int nt = 0; nt < 2; nt++) {
                const uint32_t bb2 = (uint32_t)((wnS + nt * 8) * FW) * 4 + b_off + kb;
                LDMX2(bhf[nt], sb + KH_ * 4 + bb2);
                LDMX2(blf[nt], sb + KL_ * 4 + bb2);
            }
#pragma unroll
            for (int mt = 0; mt < 2; mt++) {
                const uint32_t ab = (uint32_t)((wmS + mt * 16) * FW) * 4 + a_off + kb;
                uint32_t ah[4], al[4];
                LDMX4(ah, sb + QH_ * 4 + ab);
                LDMX4(al, sb + QL_ * 4 + ab);
#pragma unroll
                for (int nt = 0; nt < 2; nt++) {
                    mma_bf16(sc[mt][nt], ah, bhf[nt]);
                    mma_bf16(sc[mt][nt], ah, blf[nt]);
                    mma_bf16(sc[mt][nt], al, bhf[nt]);
                }
            }
        }
#pragma unroll
        for (int mt = 0; mt < 2; mt++)
#pragma unroll
            for (int nt = 0; nt < 2; nt++) {
                const int row = wmS + mt * 16 + g;
                const int col = wnS + nt * 8 + 2 * tg;
                *(float2*)&sf[SS_ + row * SSW + col] =
                    make_float2(sc[mt][nt][0] * 0.125f, sc[mt][nt][1] * 0.125f);
                *(float2*)&sf[SS_ + (row + 8) * SSW + col] =
                    make_float2(sc[mt][nt][2] * 0.125f, sc[mt][nt][3] * 0.125f);
            }
        __syncthreads();

        {
            const int r = tid >> 2, sub = tid & 3;
            const float* row = &sf[SS_ + r * SSW + sub * 16];
            float vb[16];
            float mx = row[0];
#pragma unroll
            for (int i = 0; i < 16; i++) { vb[i] = row[i]; mx = fmaxf(mx, vb[i]); }
            mx = fmaxf(mx, __shfl_xor_sync(0xffffffffu, mx, 1));
            mx = fmaxf(mx, __shfl_xor_sync(0xffffffffu, mx, 2));
            const float mo = sf[RM_ + r];
            const float mn = fmaxf(mo, mx);
            float sum = 0.f;
            uint32_t hw8[8], lw8[8];
#pragma unroll
            for (int i = 0; i < 8; i++) {
                const float p0 = fexp(vb[2 * i] - mn);
                const float p1 = fexp(vb[2 * i + 1] - mn);
                sum += p0 + p1;
                split_pack(p0, p1, hw8[i], lw8[i]);
            }
            sum += __shfl_xor_sync(0xffffffffu, sum, 1);
            sum += __shfl_xor_sync(0xffffffffu, sum, 2);
            if (sub == 0) {
                const float fct = fexp(mo - mn);
                sf[RL_ + r] = sf[RL_ + r] * fct + sum;
                sf[RM_ + r] = mn;
                sf[RF_ + r] = fct;
            }
#pragma unroll
            for (int i = 0; i < 8; i++) {
                sw[PH_ + r * FW + sub * 8 + i] = hw8[i];
                sw[PL_ + r * FW + sub * 8 + i] = lw8[i];
            }
        }
        __syncthreads();

#pragma unroll
        for (int nt = 0; nt < 4; nt++) {
            const float f0 = sf[RF_ + wnO + 8 * nt + 2 * tg];
            const float f1 = sf[RF_ + wnO + 8 * nt + 2 * tg + 1];
            oc[nt][0] *= f0; oc[nt][1] *= f1; oc[nt][2] *= f0; oc[nt][3] *= f1;
        }
#pragma unroll
        for (int ks = 0; ks < 4; ks++) {
            const uint32_t kb = ks * 32;
            const uint32_t ab = (uint32_t)(wmO * FW) * 4 + a_off + kb;
            uint32_t ah[4], al[4];
            LDMX4(ah, sb + VH_ * 4 + ab);
            LDMX4(al, sb + VL_ * 4 + ab);
#pragma unroll
            for (int nt = 0; nt < 4; nt++) {
                const uint32_t bb2 = (uint32_t)((wnO + nt * 8) * FW) * 4 + b_off + kb;
                uint32_t bhf[2], blf[2];
                LDMX2(bhf, sb + PH_ * 4 + bb2);
                LDMX2(blf, sb + PL_ * 4 + bb2);
                mma_bf16(oc[nt], ah, bhf);
                mma_bf16(oc[nt], ah, blf);
                mma_bf16(oc[nt], al, bhf);
            }
        }
    }

    // ---- finalize: emit bf16 hi/lo planes of attn output ----
    const int bb = bh >> 4, hh = bh & 15;
#pragma unroll
    for (int nt = 0; nt < 4; nt++) {
        const int qq = wnO + 8 * nt + 2 * tg;
        const float li0 = 1.f / sf[RL_ + qq];
        const float li1 = 1.f / sf[RL_ + qq + 1];
        const int d = wmO + g;
        const size_t i0 = ((size_t)(bb * T_ + q0 + qq)) * E_ + hh * 64 + d;
        const size_t i1 = i0 + E_;
        store_hl(i0,     oc[nt][0] * li0);
        store_hl(i1,     oc[nt][1] * li1);
        store_hl(i0 + 8, oc[nt][2] * li0);
        store_hl(i1 + 8, oc[nt][3] * li1);
    }
}

// ---------------------------------------------------------------------------
extern "C" void kernel_launch(void* const* d_in, const int* in_sizes, int n_in,
                              void* d_out, int out_size)
{
    const float* query     = (const float*)d_in[0];
    const float* positions = (const float*)d_in[1];
    const float* in_w      = (const float*)d_in[2];
    const float* in_b      = (const float*)d_in[3];
    const float* out_w     = (const float*)d_in[4];
    const float* out_b     = (const float*)d_in[5];
    const float* freqs     = (const float*)d_in[6];
    float* out = (float*)d_out;

    cudaFuncSetAttribute(tc_gemm,
                         cudaFuncAttributeMaxDynamicSharedMemorySize,
                         GEMM_SMEM_WORDS * (int)sizeof(uint32_t));
    cudaFuncSetAttribute(flash_kernel,
                         cudaFuncAttributeMaxDynamicSharedMemorySize,
                         FAB_WORDS * (int)sizeof(uint32_t));

    // 0) pre-convert fp32 -> bf16 hi/lo planes
    convert_kernel<<<(M_ * E_ / 2 + 255) / 256, 256>>>(query, M_ * E_ / 2, 0);
    convert_kernel<<<(N3_ * E_ / 2 + 255) / 256, 256>>>(in_w, N3_ * E_ / 2, 1);
    convert_kernel<<<(E_ * E_ / 2 + 255) / 256, 256>>>(out_w, E_ * E_ / 2, 2);

    // 1) QKV projection (cp.async planes + mma), scattered head-major
    tc_gemm<<<dim3(N3_ / 128, M_ / 128), 512,
              GEMM_SMEM_WORDS * (int)sizeof(uint32_t)>>>(in_b, nullptr, N3_, E_, 1);
    // 2) rotary on Q and K
    rotary_kernel<<<(B_ * H_ * T_ * F_) / 256, 256>>>(positions, freqs);
    // 3) attention (emits attn planes)
    flash_kernel<<<dim3(T_ / 128, B_ * H_), 512,
                   FAB_WORDS * (int)sizeof(uint32_t)>>>();
    // 4) output projection
    tc_gemm<<<dim3(E_ / 128, M_ / 128), 512,
              GEMM_SMEM_WORDS * (int)sizeof(uint32_t)>>>(out_b, out, E_, E_, 2);
}